// round 6
// baseline (speedup 1.0000x reference)
#include <cuda_runtime.h>
#include <math.h>
#include <stdint.h>

#define TB 2
#define TT 2048
#define TC 1024
#define NH 16
#define HD 64
#define BHN (TB*NH)
#define MROWS (TB*TT)
#define SCALE 0.125f

#define PQ 68   // pitch for Q/K tiles
#define PVV 72  // pitch for V/E tiles

#define NELEM ((size_t)BHN*TT*HD)

// Scratch: pre-transformed tf32 operands in head layout [b*NH+h][t][64]
__device__ __align__(16) uint32_t g_qsh[NELEM], g_qsl[NELEM];  // q*scale hi/lo
__device__ __align__(16) uint32_t g_qah[NELEM], g_qal[NELEM];  // qa hi/lo
__device__ __align__(16) uint32_t g_kh [NELEM], g_kl [NELEM];  // k hi/lo
__device__ __align__(16) uint32_t g_kah[NELEM], g_kal[NELEM];  // ka hi/lo
__device__ __align__(16) uint32_t g_v32[NELEM];                // tf32(x)
__device__ __align__(16) uint32_t g_e32[NELEM];                // tf32(x[s+1]-y[s])
__device__ __align__(16) float    g_y  [NELEM];
__device__ __align__(16) float    g_ysum[(size_t)TB*TT*TC];

__device__ __forceinline__ uint32_t f2tf32(float f) {
    uint32_t u;
    asm volatile("cvt.rna.tf32.f32 %0, %1;" : "=r"(u) : "f"(f));
    return u;
}
__device__ __forceinline__ void split_tf32(float v, uint32_t& hi, uint32_t& lo) {
    hi = f2tf32(v);
    lo = f2tf32(v - __uint_as_float(hi));
}
__device__ __forceinline__ void mma_tf32(float c[4], const uint32_t a[4],
                                         const uint32_t b[2]) {
    asm volatile(
        "mma.sync.aligned.m16n8k8.row.col.f32.tf32.tf32.f32 "
        "{%0,%1,%2,%3}, {%4,%5,%6,%7}, {%8,%9}, {%0,%1,%2,%3};"
        : "+f"(c[0]), "+f"(c[1]), "+f"(c[2]), "+f"(c[3])
        : "r"(a[0]), "r"(a[1]), "r"(a[2]), "r"(a[3]), "r"(b[0]), "r"(b[1]));
}
__device__ __forceinline__ uint32_t s2u(const void* p) {
    return (uint32_t)__cvta_generic_to_shared(p);
}
__device__ __forceinline__ void cp_async16(uint32_t dst, const void* src) {
    asm volatile("cp.async.cg.shared.global [%0], [%1], 16;"
                 :: "r"(dst), "l"(src));
}
#define CP_COMMIT() asm volatile("cp.async.commit_group;")
#define CP_WAIT1()  asm volatile("cp.async.wait_group 1;" ::: "memory")

// ---------------------------------------------------------------------------
// prep: v32 = tf32(x) gathered into head layout
// ---------------------------------------------------------------------------
__global__ __launch_bounds__(256)
void prep_v32_kernel(const float* __restrict__ x)
{
    size_t i = (((size_t)blockIdx.x * 256 + threadIdx.x) << 2);
    int d  = (int)(i & 63);
    int t  = (int)((i >> 6) & (TT - 1));
    int bh = (int)(i >> 17);
    int b = bh >> 4, h = bh & 15;
    float4 v = *(const float4*)(x + ((size_t)b * TT + t) * TC + h * 64 + d);
    *(uint4*)(g_v32 + i) =
        make_uint4(f2tf32(v.x), f2tf32(v.y), f2tf32(v.z), f2tf32(v.w));
}

// ---------------------------------------------------------------------------
// TF32 tensor-core GEMM; epilogues fold the attention operand transforms.
// ---------------------------------------------------------------------------
template<int MODE>
__global__ __launch_bounds__(256)
void tgemm_kernel(const float* __restrict__ A, const float* __restrict__ Bw,
                  float* __restrict__ Cout, int M, int N, int K)
{
    __shared__ uint32_t As[16][136];
    __shared__ uint32_t Bs[16][136];

    const int tid = threadIdx.x;
    const int lane = tid & 31;
    const int warp = tid >> 5;
    const int warpM = warp >> 2;
    const int warpN = warp & 3;
    const int g = lane >> 2;
    const int t = lane & 3;

    const int bm = blockIdx.y * 128;
    const int bn = blockIdx.x * 128;
    const float* Ap = (MODE == 2) ? (const float*)g_ysum : A;

    float acc[4][4][4];
#pragma unroll
    for (int i = 0; i < 4; i++)
#pragma unroll
        for (int j = 0; j < 4; j++)
#pragma unroll
            for (int r = 0; r < 4; r++) acc[i][j][r] = 0.f;

    const int aRow0 = tid >> 2,            aq0 = (tid & 3) << 2;
    const int aRow1 = (tid + 256) >> 2,    aq1 = aq0;
    const int bRow0 = tid >> 5,            bc0 = (tid & 31) << 2;
    const int bRow1 = (tid + 256) >> 5,    bc1 = bc0;

    float4 pa0, pa1, pb0, pb1;
    pa0 = *(const float4*)(Ap + (size_t)(bm + aRow0) * K + aq0);
    pa1 = *(const float4*)(Ap + (size_t)(bm + aRow1) * K + aq1);
    pb0 = *(const float4*)(Bw + (size_t)(bRow0) * N + bn + bc0);
    pb1 = *(const float4*)(Bw + (size_t)(bRow1) * N + bn + bc1);

    for (int kt = 0; kt < K; kt += 16) {
        __syncthreads();
        As[aq0 + 0][aRow0] = f2tf32(pa0.x);
        As[aq0 + 1][aRow0] = f2tf32(pa0.y);
        As[aq0 + 2][aRow0] = f2tf32(pa0.z);
        As[aq0 + 3][aRow0] = f2tf32(pa0.w);
        As[aq1 + 0][aRow1] = f2tf32(pa1.x);
        As[aq1 + 1][aRow1] = f2tf32(pa1.y);
        As[aq1 + 2][aRow1] = f2tf32(pa1.z);
        As[aq1 + 3][aRow1] = f2tf32(pa1.w);
        Bs[bRow0][bc0 + 0] = f2tf32(pb0.x);
        Bs[bRow0][bc0 + 1] = f2tf32(pb0.y);
        Bs[bRow0][bc0 + 2] = f2tf32(pb0.z);
        Bs[bRow0][bc0 + 3] = f2tf32(pb0.w);
        Bs[bRow1][bc1 + 0] = f2tf32(pb1.x);
        Bs[bRow1][bc1 + 1] = f2tf32(pb1.y);
        Bs[bRow1][bc1 + 2] = f2tf32(pb1.z);
        Bs[bRow1][bc1 + 3] = f2tf32(pb1.w);
        __syncthreads();

        if (kt + 16 < K) {
            int kn = kt + 16;
            pa0 = *(const float4*)(Ap + (size_t)(bm + aRow0) * K + kn + aq0);
            pa1 = *(const float4*)(Ap + (size_t)(bm + aRow1) * K + kn + aq1);
            pb0 = *(const float4*)(Bw + (size_t)(kn + bRow0) * N + bn + bc0);
            pb1 = *(const float4*)(Bw + (size_t)(kn + bRow1) * N + bn + bc1);
        }

#pragma unroll
        for (int ks = 0; ks < 2; ks++) {
            const int k0 = ks * 8;
            uint32_t af[4][4], bf[4][2];
#pragma unroll
            for (int i = 0; i < 4; i++) {
                int m0 = warpM * 64 + i * 16;
                af[i][0] = As[k0 + t][m0 + g];
                af[i][1] = As[k0 + t][m0 + g + 8];
                af[i][2] = As[k0 + t + 4][m0 + g];
                af[i][3] = As[k0 + t + 4][m0 + g + 8];
            }
#pragma unroll
            for (int j = 0; j < 4; j++) {
                int n0 = warpN * 32 + j * 8;
                bf[j][0] = Bs[k0 + t][n0 + g];
                bf[j][1] = Bs[k0 + t + 4][n0 + g];
            }
#pragma unroll
            for (int i = 0; i < 4; i++)
#pragma unroll
                for (int j = 0; j < 4; j++)
                    mma_tf32(acc[i][j], af[i], bf[j]);
        }
    }

#pragma unroll
    for (int i = 0; i < 4; i++) {
#pragma unroll
        for (int j = 0; j < 4; j++) {
            int col = bn + warpN * 32 + j * 8 + t * 2;
#pragma unroll
            for (int half = 0; half < 2; half++) {
                int m = bm + warpM * 64 + i * 16 + g + half * 8;
                float2 v = half == 0 ? make_float2(acc[i][j][0], acc[i][j][1])
                                     : make_float2(acc[i][j][2], acc[i][j][3]);
                if (MODE == 2) {
                    *(float2*)(Cout + (size_t)m * N + col) = v;
                } else {
                    int b = m >> 11;
                    int tt = m & (TT - 1);
                    uint32_t h0, l0, h1, l1;
                    if (MODE == 0) {
                        if (col < TC) {
                            int h = col >> 6, dd = col & 63;
                            size_t off =
                                (((size_t)(b * NH + h) * TT + tt) << 6) + dd;
                            float q0 = v.x * SCALE, q1 = v.y * SCALE;
                            split_tf32(q0, h0, l0); split_tf32(q1, h1, l1);
                            *(uint2*)(g_qsh + off) = make_uint2(h0, h1);
                            *(uint2*)(g_qsl + off) = make_uint2(l0, l1);
                            float a0 = fminf(q0, 0.02f * q0);
                            float a1 = fminf(q1, 0.02f * q1);
                            split_tf32(a0, h0, l0); split_tf32(a1, h1, l1);
                            *(uint2*)(g_qah + off) = make_uint2(h0, h1);
                            *(uint2*)(g_qal + off) = make_uint2(l0, l1);
                        } else {
                            int nn = col - TC;
                            int h = nn >> 6, dd = nn & 63;
                            size_t off =
                                (((size_t)(b * NH + h) * TT + tt) << 6) + dd;
                            split_tf32(v.x, h0, l0); split_tf32(v.y, h1, l1);
                            *(uint2*)(g_kh + off) = make_uint2(h0, h1);
                            *(uint2*)(g_kl + off) = make_uint2(l0, l1);
                        }
                    } else {
                        int h = col >> 6, dd = col & 63;
                        size_t off =
                            (((size_t)(b * NH + h) * TT + tt) << 6) + dd;
                        float ka0 = 1.f / (1.f + __expf(-0.0025f * v.x));
                        float ka1 = 1.f / (1.f + __expf(-0.0025f * v.y));
                        split_tf32(ka0, h0, l0); split_tf32(ka1, h1, l1);
                        *(uint2*)(g_kah + off) = make_uint2(h0, h1);
                        *(uint2*)(g_kal + off) = make_uint2(l0, l1);
                    }
                }
            }
        }
    }
}

// ---------------------------------------------------------------------------
// Fused tensor-core attention, 256 threads (8 warps), 64q x 32s tiles with a
// TWO-STAGE cp.async pipeline (loads of tile st+2 overlap compute of tile st).
// Warp (wm, wn): q-rows [wm*16,+16), s-cols [wn*16,+16) of each 32-s tile.
// Warp-local online softmax; the two wn stripes merge once at the end.
// smem: Q hi/lo [64][PQ] + K hi/lo [2][32][PQ] + V [2][32][PVV] = 88064 B.
// ---------------------------------------------------------------------------
template<int ARMA>
__global__ __launch_bounds__(256)
void fattn_kernel(const float* __restrict__ x)
{
    extern __shared__ float sm[];
    float* Qh = sm;                    // [64][PQ]
    float* Ql = Qh + 64 * PQ;
    float* Kh = Ql + 64 * PQ;          // [2][32][PQ]
    float* Kl = Kh + 2 * 32 * PQ;
    float* Vh = Kl + 2 * 32 * PQ;      // [2][32][PVV]

    const int tid = threadIdx.x;
    const int lane = tid & 31;
    const int warp = tid >> 5;
    const int wm = warp >> 1;
    const int wn = warp & 1;
    const int g = lane >> 2;
    const int t = lane & 3;

    const int bh = blockIdx.y;
    const int b = bh >> 4, h = bh & 15;
    const int qb = (int)gridDim.x - 1 - (int)blockIdx.x;  // heavy first
    const int q0 = qb * 64;
    const int nst = 2 * (qb + 1);      // number of 32-row s-tiles

    const uint32_t* qh_g = (ARMA ? g_qah : g_qsh) + (size_t)bh * TT * HD;
    const uint32_t* ql_g = (ARMA ? g_qal : g_qsl) + (size_t)bh * TT * HD;
    const uint32_t* kh_g = (ARMA ? g_kah : g_kh) + (size_t)bh * TT * HD;
    const uint32_t* kl_g = (ARMA ? g_kal : g_kl) + (size_t)bh * TT * HD;
    const uint32_t* v_g  = (ARMA ? g_e32 : g_v32) + (size_t)bh * TT * HD;
    const float* yb = g_y + (size_t)bh * TT * HD;
    const float* vx = x + (size_t)b * TT * TC + h * HD;

    const int lr = tid >> 4;           // 0..15
    const int lc4 = (tid & 15) << 2;   // 0..60

    const uint32_t Qh_s = s2u(Qh), Ql_s = s2u(Ql);
    const uint32_t Kh_s = s2u(Kh), Kl_s = s2u(Kl), Vh_s = s2u(Vh);

    // ---- stage Q (group 0, with tile 0)
#pragma unroll
    for (int it = 0; it < 4; it++) {
        int r = lr + it * 16;
        cp_async16(Qh_s + (r * PQ + lc4) * 4, qh_g + (size_t)(q0 + r) * HD + lc4);
        cp_async16(Ql_s + (r * PQ + lc4) * 4, ql_g + (size_t)(q0 + r) * HD + lc4);
    }
    // ---- stage tiles 0 and 1 (nst >= 2 always)
#pragma unroll
    for (int st = 0; st < 2; st++) {
#pragma unroll
        for (int it = 0; it < 2; it++) {
            int r = lr + it * 16;                 // 0..31
            size_t s = (size_t)(st * 32 + r) * HD + lc4;
            int roff = (st * 32 + r);
            cp_async16(Kh_s + (roff * PQ + lc4) * 4, kh_g + s);
            cp_async16(Kl_s + (roff * PQ + lc4) * 4, kl_g + s);
            cp_async16(Vh_s + (roff * PVV + lc4) * 4, v_g + s);
        }
        CP_COMMIT();
    }

    float O[8][4];
#pragma unroll
    for (int n = 0; n < 8; n++)
#pragma unroll
        for (int c = 0; c < 4; c++) O[n][c] = 0.f;
    float m_run[2] = {-1e30f, -1e30f};
    float l_run[2] = {0.f, 0.f};

    const int qrow0 = q0 + wm * 16 + g;
    const int qrow1 = qrow0 + 8;
    const int mr = wm * 16 + g;

    const uint32_t* Qhu = (const uint32_t*)Qh;
    const uint32_t* Qlu = (const uint32_t*)Ql;
    const uint32_t* Khu = (const uint32_t*)Kh;
    const uint32_t* Klu = (const uint32_t*)Kl;
    const uint32_t* Vhu = (const uint32_t*)Vh;

    for (int st = 0; st < nst; st++) {
        const int stage = st & 1;
        const int s0 = st * 32;
        CP_WAIT1();          // tile st landed (tile st+1 may still be in flight)
        __syncthreads();

        // ---- S = Q @ K^T over this warp's 16 s-cols (3xTF32)
        float acc[2][4];
#pragma unroll
        for (int nb = 0; nb < 2; nb++)
#pragma unroll
            for (int c = 0; c < 4; c++) acc[nb][c] = 0.f;

#pragma unroll
        for (int k0 = 0; k0 < 64; k0 += 8) {
            uint32_t ah[4], al[4];
            ah[0] = Qhu[mr * PQ + k0 + t];
            ah[1] = Qhu[(mr + 8) * PQ + k0 + t];
            ah[2] = Qhu[mr * PQ + k0 + t + 4];
            ah[3] = Qhu[(mr + 8) * PQ + k0 + t + 4];
            al[0] = Qlu[mr * PQ + k0 + t];
            al[1] = Qlu[(mr + 8) * PQ + k0 + t];
            al[2] = Qlu[mr * PQ + k0 + t + 4];
            al[3] = Qlu[(mr + 8) * PQ + k0 + t + 4];
#pragma unroll
            for (int nb = 0; nb < 2; nb++) {
                int sr = stage * 32 + wn * 16 + nb * 8 + g;
                uint32_t bh2[2], bl2[2];
                bh2[0] = Khu[sr * PQ + k0 + t];
                bh2[1] = Khu[sr * PQ + k0 + t + 4];
                bl2[0] = Klu[sr * PQ + k0 + t];
                bl2[1] = Klu[sr * PQ + k0 + t + 4];
                mma_tf32(acc[nb], ah, bh2);
                mma_tf32(acc[nb], al, bh2);
                mma_tf32(acc[nb], ah, bl2);
            }
        }

        const bool diag = (st >= 2 * qb);   // last two tiles overlap diagonal
        if (diag) {
#pragma unroll
            for (int nb = 0; nb < 2; nb++) {
                int colb = s0 + wn * 16 + nb * 8 + 2 * t;
#pragma unroll
                for (int c = 0; c < 4; c++) {
                    int cc = colb + (c & 1);
                    int rr = (c >= 2) ? qrow1 : qrow0;
                    if (ARMA) { if (cc >= rr) acc[nb][c] = 0.f; }
                    else      { if (cc >  rr) acc[nb][c] = -1e30f; }
                }
            }
        }

        if (!ARMA) {
            float mt0 = -1e30f, mt1 = -1e30f;
#pragma unroll
            for (int nb = 0; nb < 2; nb++) {
                mt0 = fmaxf(mt0, fmaxf(acc[nb][0], acc[nb][1]));
                mt1 = fmaxf(mt1, fmaxf(acc[nb][2], acc[nb][3]));
            }
#pragma unroll
            for (int off = 1; off <= 2; off <<= 1) {
                mt0 = fmaxf(mt0, __shfl_xor_sync(0xffffffffu, mt0, off));
                mt1 = fmaxf(mt1, __shfl_xor_sync(0xffffffffu, mt1, off));
            }
            float mn0 = fmaxf(m_run[0], mt0);
            float mn1 = fmaxf(m_run[1], mt1);
            float corr0 = __expf(m_run[0] - mn0);
            float corr1 = __expf(m_run[1] - mn1);
            m_run[0] = mn0; m_run[1] = mn1;

            float ls0 = 0.f, ls1 = 0.f;
#pragma unroll
            for (int nb = 0; nb < 2; nb++) {
                float p0 = __expf(acc[nb][0] - mn0);
                float p1 = __expf(acc[nb][1] - mn0);
                float p2 = __expf(acc[nb][2] - mn1);
                float p3 = __expf(acc[nb][3] - mn1);
                if (diag) {
                    int colb = s0 + wn * 16 + nb * 8 + 2 * t;
                    if (colb     > qrow0) p0 = 0.f;
                    if (colb + 1 > qrow0) p1 = 0.f;
                    if (colb     > qrow1) p2 = 0.f;
                    if (colb + 1 > qrow1) p3 = 0.f;
                }
                acc[nb][0] = p0; acc[nb][1] = p1;
                acc[nb][2] = p2; acc[nb][3] = p3;
                ls0 += p0 + p1;
                ls1 += p2 + p3;
            }
#pragma unroll
            for (int off = 1; off <= 2; off <<= 1) {
                ls0 += __shfl_xor_sync(0xffffffffu, ls0, off);
                ls1 += __shfl_xor_sync(0xffffffffu, ls1, off);
            }
            l_run[0] = l_run[0] * corr0 + ls0;
            l_run[1] = l_run[1] * corr1 + ls1;
#pragma unroll
            for (int n = 0; n < 8; n++) {
                O[n][0] *= corr0; O[n][1] *= corr0;
                O[n][2] *= corr1; O[n][3] *= corr1;
            }
        }

        // ---- O += P @ V : P via shfl (registers only)
#pragma unroll
        for (int nb = 0; nb < 2; nb++) {
            int src0 = (lane & ~3) | (t >> 1);
            int src2 = src0 + 2;
            float s00 = __shfl_sync(0xffffffffu, acc[nb][0], src0);
            float s01 = __shfl_sync(0xffffffffu, acc[nb][1], src0);
            float s20 = __shfl_sync(0xffffffffu, acc[nb][0], src2);
            float s21 = __shfl_sync(0xffffffffu, acc[nb][1], src2);
            float s10 = __shfl_sync(0xffffffffu, acc[nb][2], src0);
            float s11 = __shfl_sync(0xffffffffu, acc[nb][3], src0);
            float s30 = __shfl_sync(0xffffffffu, acc[nb][2], src2);
            float s31 = __shfl_sync(0xffffffffu, acc[nb][3], src2);
            bool odd = (t & 1);
            float pa0 = odd ? s01 : s00;
            float pa1 = odd ? s11 : s10;
            float pa2 = odd ? s21 : s20;
            float pa3 = odd ? s31 : s30;
            uint32_t ah[4], al[4];
            split_tf32(pa0, ah[0], al[0]);
            split_tf32(pa1, ah[1], al[1]);
            split_tf32(pa2, ah[2], al[2]);
            split_tf32(pa3, ah[3], al[3]);
            int srow = stage * 32 + wn * 16 + nb * 8;
#pragma unroll
            for (int n = 0; n < 8; n++) {
                uint32_t bv[2];
                bv[0] = Vhu[(srow + t) * PVV + n * 8 + g];
                bv[1] = Vhu[(srow + t + 4) * PVV + n * 8 + g];
                mma_tf32(O[n], ah, bv);
                mma_tf32(O[n], al, bv);
            }
        }

        __syncthreads();   // all warps done reading buffer `stage`
        // ---- stage tile st+2 into buffer `stage` (overlaps next compute)
        if (st + 2 < nst) {
#pragma unroll
            for (int it = 0; it < 2; it++) {
                int r = lr + it * 16;
                size_t s = (size_t)((st + 2) * 32 + r) * HD + lc4;
                int roff = (stage * 32 + r);
                cp_async16(Kh_s + (roff * PQ + lc4) * 4, kh_g + s);
                cp_async16(Kl_s + (roff * PQ + lc4) * 4, kl_g + s);
                cp_async16(Vh_s + (roff * PVV + lc4) * 4, v_g + s);
            }
        }
        CP_COMMIT();
    }

    // ---- merge the two wn stripes once, write out
    __syncthreads();
    const int r0l = wm * 16 + g, r1l = r0l + 8;
    float* Ob = Qh;            // reuse smem, pitch 66
    if (!ARMA) {
        float* ml = Kh;
        if (t == 0) {
            ml[r0l * 4 + wn * 2 + 0] = m_run[0];
            ml[r0l * 4 + wn * 2 + 1] = l_run[0];
            ml[r1l * 4 + wn * 2 + 0] = m_run[1];
            ml[r1l * 4 + wn * 2 + 1] = l_run[1];
        }
        __syncthreads();
        float ma0 = ml[r0l * 4 + 0], la0 = ml[r0l * 4 + 1];
        float mb0 = ml[r0l * 4 + 2], lb0 = ml[r0l * 4 + 3];
        float ma1 = ml[r1l * 4 + 0], la1 = ml[r1l * 4 + 1];
        float mb1 = ml[r1l * 4 + 2], lb1 = ml[r1l * 4 + 3];
        float mm0 = fmaxf(ma0, mb0), mm1 = fmaxf(ma1, mb1);
        float lt0 = la0 * __expf(ma0 - mm0) + lb0 * __expf(mb0 - mm0);
        float lt1 = la1 * __expf(ma1 - mm1) + lb1 * __expf(mb1 - mm1);
        float f0 = __expf(m_run[0] - mm0);
        float f1 = __expf(m_run[1] - mm1);
#pragma unroll
        for (int n = 0; n < 8; n++) {
            O[n][0] *= f0; O[n][1] *= f0;
            O[n][2] *= f1; O[n][3] *= f1;
        }
        if (wn == 1) {
#pragma unroll
            for (int n = 0; n < 8; n++) {
                int col = n * 8 + 2 * t;
                *(float2*)(Ob + r0l * 66 + col) = make_float2(O[n][0], O[n][1]);
                *(float2*)(Ob + r1l * 66 + col) = make_float2(O[n][2], O[n][3]);
            }
        }
        __syncthreads();
        if (wn == 0) {
            float inv0 = 1.f / lt0, inv1 = 1.f / lt1;
            float* yo = g_y + (size_t)bh * TT * HD;
            uint32_t* eo = g_e32 + (size_t)bh * TT * HD;
#pragma unroll
            for (int n = 0; n < 8; n++) {
                int col = n * 8 + 2 * t;
                float2 p0 = *(const float2*)(Ob + r0l * 66 + col);
                float2 p1 = *(const float2*)(Ob + r1l * 66 + col);
                float y00 = (O[n][0] + p0.x) * inv0;
                float y01 = (O[n][1] + p0.y) * inv0;
                float y10 = (O[n][2] + p1.x) * inv1;
                float y11 = (O[n][3] + p1.y) * inv1;
                *(float2*)(yo + (size_t)qrow0 * HD + col) = make_float2(y00, y01);
                *(float2*)(yo + (size_t)qrow1 * HD + col) = make_float2(y10, y11);
                float e00 = 0.f, e01 = 0.f, e10 = 0.f, e11 = 0.f;
                if (qrow0 + 1 < TT) {
                    float2 xv = *(const float2*)(vx + (size_t)(qrow0 + 1) * TC + col);
                    e00 = xv.x - y00; e01 = xv.y - y01;
                }
                if (qrow1 + 1 < TT) {
                    float2 xv = *(const float2*)(vx + (size_t)(qrow1 + 1) * TC + col);
                    e10 = xv.x - y10; e11 = xv.y - y11;
                }
                *(uint2*)(eo + (size_t)qrow0 * HD + col) =
                    make_uint2(f2tf32(e00), f2tf32(e01));
                *(uint2*)(eo + (size_t)qrow1 * HD + col) =
                    make_uint2(f2tf32(e10), f2tf32(e11));
            }
        }
    } else {
        if (wn == 1) {
#pragma unroll
            for (int n = 0; n < 8; n++) {
                int col = n * 8 + 2 * t;
                *(float2*)(Ob + r0l * 66 + col) = make_float2(O[n][0], O[n][1]);
                *(float2*)(Ob + r1l * 66 + col) = make_float2(O[n][2], O[n][3]);
            }
        }
        __syncthreads();
        if (wn == 0) {
            float* yo = g_ysum + (size_t)b * TT * TC + h * HD;
#pragma unroll
            for (int n = 0; n < 8; n++) {
                int col = n * 8 + 2 * t;
                float2 p0 = *(const float2*)(Ob + r0l * 66 + col);
                float2 p1 = *(const float2*)(Ob + r1l * 66 + col);
                float2 y0 = *(const float2*)(yb + (size_t)qrow0 * HD + col);
                float2 y1 = *(const float2*)(yb + (size_t)qrow1 * HD + col);
                *(float2*)(yo + (size_t)qrow0 * TC + col) =
                    make_float2(O[n][0] + p0.x + y0.x, O[n][1] + p0.y + y0.y);
                *(float2*)(yo + (size_t)qrow1 * TC + col) =
                    make_float2(O[n][2] + p1.x + y1.x, O[n][3] + p1.y + y1.y);
            }
        }
    }
}

// ---------------------------------------------------------------------------
extern "C" void kernel_launch(void* const* d_in, const int* in_sizes, int n_in,
                              void* d_out, int out_size)
{
    (void)in_sizes; (void)n_in; (void)out_size;
    const float* x      = (const float*)d_in[0];
    const float* W_attn = (const float*)d_in[1];
    const float* W_k2   = (const float*)d_in[2];
    const float* W_proj = (const float*)d_in[3];
    float* out = (float*)d_out;

    const int smem_attn =
        (2 * 64 * PQ + 2 * 32 * PQ * 2 + 2 * 32 * PVV) * (int)sizeof(float); // 88064
    cudaFuncSetAttribute(fattn_kernel<0>,
                         cudaFuncAttributeMaxDynamicSharedMemorySize, smem_attn);
    cudaFuncSetAttribute(fattn_kernel<1>,
                         cudaFuncAttributeMaxDynamicSharedMemorySize, smem_attn);

    dim3 blk(256);
    prep_v32_kernel<<<(int)(NELEM / 4 / 256), 256>>>(x);
    tgemm_kernel<0><<<dim3(2 * TC / 128, MROWS / 128), blk>>>(
        x, W_attn, nullptr, MROWS, 2 * TC, TC);
    tgemm_kernel<1><<<dim3(TC / 128, MROWS / 128), blk>>>(
        x, W_k2, nullptr, MROWS, TC, TC);
    fattn_kernel<0><<<dim3(TT / 64, BHN), 256, smem_attn>>>(x);
    fattn_kernel<1><<<dim3(TT / 64, BHN), 256, smem_attn>>>(x);
    tgemm_kernel<2><<<dim3(TC / 128, MROWS / 128), blk>>>(
        nullptr, W_proj, out, MROWS, TC, TC);
}

// round 7
// speedup vs baseline: 1.1273x; 1.1273x over previous
#include <cuda_runtime.h>
#include <math.h>
#include <stdint.h>

#define TB 2
#define TT 2048
#define TC 1024
#define NH 16
#define HD 64
#define BHN (TB*NH)
#define MROWS (TB*TT)
#define SCALE 0.125f

#define NELEM ((size_t)BHN*TT*HD)

// Frag-major scratch. Per bh: Q arrays = (TT/16) blocks * 1024 words;
// K/V arrays = (TT/8) blocks * 512 words. Both = TT*64 words per bh.
__device__ __align__(16) uint32_t g_qsh[NELEM], g_qsl[NELEM];  // q*scale hi/lo
__device__ __align__(16) uint32_t g_qah[NELEM], g_qal[NELEM];  // qa hi/lo
__device__ __align__(16) uint32_t g_kh [NELEM], g_kl [NELEM];  // k hi/lo
__device__ __align__(16) uint32_t g_kah[NELEM], g_kal[NELEM];  // ka hi/lo
__device__ __align__(16) uint32_t g_v32[NELEM];                // tf32(x)
__device__ __align__(16) uint32_t g_e32[NELEM];                // tf32(x[s+1]-y[s])
__device__ __align__(16) float    g_y  [NELEM];
__device__ __align__(16) float    g_ysum[(size_t)TB*TT*TC];

__device__ __forceinline__ uint32_t f2tf32(float f) {
    uint32_t u;
    asm volatile("cvt.rna.tf32.f32 %0, %1;" : "=r"(u) : "f"(f));
    return u;
}
__device__ __forceinline__ void split_tf32(float v, uint32_t& hi, uint32_t& lo) {
    hi = f2tf32(v);
    lo = f2tf32(v - __uint_as_float(hi));
}
__device__ __forceinline__ void mma_tf32(float c[4], const uint32_t a[4],
                                         const uint32_t b[2]) {
    asm volatile(
        "mma.sync.aligned.m16n8k8.row.col.f32.tf32.tf32.f32 "
        "{%0,%1,%2,%3}, {%4,%5,%6,%7}, {%8,%9}, {%0,%1,%2,%3};"
        : "+f"(c[0]), "+f"(c[1]), "+f"(c[2]), "+f"(c[3])
        : "r"(a[0]), "r"(a[1]), "r"(a[2]), "r"(a[3]), "r"(b[0]), "r"(b[1]));
}
__device__ __forceinline__ uint32_t s2u(const void* p) {
    return (uint32_t)__cvta_generic_to_shared(p);
}
__device__ __forceinline__ void cp_async16(uint32_t dst, const void* src) {
    asm volatile("cp.async.cg.shared.global [%0], [%1], 16;"
                 :: "r"(dst), "l"(src));
}
#define CP_COMMIT() asm volatile("cp.async.commit_group;")
#define CP_WAIT0()  asm volatile("cp.async.wait_group 0;" ::: "memory")

// ---- frag-layout index helpers (swizzle baked into word order) ----
// A-frag (Q): lane=((r&7)<<2)|(d&3); word=((c+lane&7 ...)):
__device__ __forceinline__ size_t qfrag_idx(int tt, int dd) {
    int lane = ((tt & 7) << 2) | (dd & 3);
    int word = (((dd >> 3) + (lane & 7)) & 7) * 4
             + ((tt >> 3) & 1) + (((dd >> 2) & 1) << 1);
    return ((size_t)(tt >> 4)) * 1024 + lane * 32 + word;
}
// B-frag (K): lane=((s&7)<<2)|(d&3); word=((c+(lane>>1))&7)*2 + half
__device__ __forceinline__ size_t kfrag_idx(int tt, int dd) {
    int lane = ((tt & 7) << 2) | (dd & 3);
    int word = (((dd >> 3) + (lane >> 1)) & 7) * 2 + ((dd >> 2) & 1);
    return ((size_t)(tt >> 3)) * 512 + lane * 16 + word;
}
// B-frag (V, d-in-cols layout): lane=((d&7)<<2)|(s&3)
__device__ __forceinline__ size_t vfrag_idx(int s, int d) {
    int lane = ((d & 7) << 2) | (s & 3);
    int n = d >> 3;
    int grp = ((s >> 2) & 1) * 2 + (n >> 2);
    int word = ((grp + (lane >> 1)) & 3) * 4 + (n & 3);
    return ((size_t)(s >> 3)) * 512 + lane * 16 + word;
}

__device__ __forceinline__ void store_q(int bh, int tt, int dd, float qraw) {
    float qs = qraw * SCALE;
    size_t flat = (size_t)bh * (TT * 64) + qfrag_idx(tt, dd);
    uint32_t h, l;
    split_tf32(qs, h, l);  g_qsh[flat] = h; g_qsl[flat] = l;
    float qa = fminf(qs, 0.02f * qs);
    split_tf32(qa, h, l);  g_qah[flat] = h; g_qal[flat] = l;
}
__device__ __forceinline__ void store_kfrag(uint32_t* gh, uint32_t* gl,
                                            int bh, int tt, int dd, float v) {
    size_t flat = (size_t)bh * (TT * 64) + kfrag_idx(tt, dd);
    uint32_t h, l;
    split_tf32(v, h, l);
    gh[flat] = h; gl[flat] = l;
}

// ---------------------------------------------------------------------------
// prep: v32 = tf32(x) scattered into V-frag layout
// ---------------------------------------------------------------------------
__global__ __launch_bounds__(256)
void prep_v32_kernel(const float* __restrict__ x)
{
    size_t i = (((size_t)blockIdx.x * 256 + threadIdx.x) << 2);
    int d  = (int)(i & 63);
    int t  = (int)((i >> 6) & (TT - 1));
    int bh = (int)(i >> 17);
    int b = bh >> 4, h = bh & 15;
    float4 v = *(const float4*)(x + ((size_t)b * TT + t) * TC + h * 64 + d);
    uint32_t* vb = g_v32 + (size_t)bh * (TT * 64);
    vb[vfrag_idx(t, d + 0)] = f2tf32(v.x);
    vb[vfrag_idx(t, d + 1)] = f2tf32(v.y);
    vb[vfrag_idx(t, d + 2)] = f2tf32(v.z);
    vb[vfrag_idx(t, d + 3)] = f2tf32(v.w);
}

// ---------------------------------------------------------------------------
// TF32 tensor-core GEMM; epilogues emit frag-major transformed operands.
// ---------------------------------------------------------------------------
template<int MODE>
__global__ __launch_bounds__(256)
void tgemm_kernel(const float* __restrict__ A, const float* __restrict__ Bw,
                  float* __restrict__ Cout, int M, int N, int K)
{
    __shared__ uint32_t As[16][136];
    __shared__ uint32_t Bs[16][136];

    const int tid = threadIdx.x;
    const int lane = tid & 31;
    const int warp = tid >> 5;
    const int warpM = warp >> 2;
    const int warpN = warp & 3;
    const int g = lane >> 2;
    const int t = lane & 3;

    const int bm = blockIdx.y * 128;
    const int bn = blockIdx.x * 128;
    const float* Ap = (MODE == 2) ? (const float*)g_ysum : A;

    float acc[4][4][4];
#pragma unroll
    for (int i = 0; i < 4; i++)
#pragma unroll
        for (int j = 0; j < 4; j++)
#pragma unroll
            for (int r = 0; r < 4; r++) acc[i][j][r] = 0.f;

    const int aRow0 = tid >> 2,            aq0 = (tid & 3) << 2;
    const int aRow1 = (tid + 256) >> 2,    aq1 = aq0;
    const int bRow0 = tid >> 5,            bc0 = (tid & 31) << 2;
    const int bRow1 = (tid + 256) >> 5,    bc1 = bc0;

    float4 pa0, pa1, pb0, pb1;
    pa0 = *(const float4*)(Ap + (size_t)(bm + aRow0) * K + aq0);
    pa1 = *(const float4*)(Ap + (size_t)(bm + aRow1) * K + aq1);
    pb0 = *(const float4*)(Bw + (size_t)(bRow0) * N + bn + bc0);
    pb1 = *(const float4*)(Bw + (size_t)(bRow1) * N + bn + bc1);

    for (int kt = 0; kt < K; kt += 16) {
        __syncthreads();
        As[aq0 + 0][aRow0] = f2tf32(pa0.x);
        As[aq0 + 1][aRow0] = f2tf32(pa0.y);
        As[aq0 + 2][aRow0] = f2tf32(pa0.z);
        As[aq0 + 3][aRow0] = f2tf32(pa0.w);
        As[aq1 + 0][aRow1] = f2tf32(pa1.x);
        As[aq1 + 1][aRow1] = f2tf32(pa1.y);
        As[aq1 + 2][aRow1] = f2tf32(pa1.z);
        As[aq1 + 3][aRow1] = f2tf32(pa1.w);
        Bs[bRow0][bc0 + 0] = f2tf32(pb0.x);
        Bs[bRow0][bc0 + 1] = f2tf32(pb0.y);
        Bs[bRow0][bc0 + 2] = f2tf32(pb0.z);
        Bs[bRow0][bc0 + 3] = f2tf32(pb0.w);
        Bs[bRow1][bc1 + 0] = f2tf32(pb1.x);
        Bs[bRow1][bc1 + 1] = f2tf32(pb1.y);
        Bs[bRow1][bc1 + 2] = f2tf32(pb1.z);
        Bs[bRow1][bc1 + 3] = f2tf32(pb1.w);
        __syncthreads();

        if (kt + 16 < K) {
            int kn = kt + 16;
            pa0 = *(const float4*)(Ap + (size_t)(bm + aRow0) * K + kn + aq0);
            pa1 = *(const float4*)(Ap + (size_t)(bm + aRow1) * K + kn + aq1);
            pb0 = *(const float4*)(Bw + (size_t)(kn + bRow0) * N + bn + bc0);
            pb1 = *(const float4*)(Bw + (size_t)(kn + bRow1) * N + bn + bc1);
        }

#pragma unroll
        for (int ks = 0; ks < 2; ks++) {
            const int k0 = ks * 8;
            uint32_t af[4][4], bf[4][2];
#pragma unroll
            for (int i = 0; i < 4; i++) {
                int m0 = warpM * 64 + i * 16;
                af[i][0] = As[k0 + t][m0 + g];
                af[i][1] = As[k0 + t][m0 + g + 8];
                af[i][2] = As[k0 + t + 4][m0 + g];
                af[i][3] = As[k0 + t + 4][m0 + g + 8];
            }
#pragma unroll
            for (int j = 0; j < 4; j++) {
                int n0 = warpN * 32 + j * 8;
                bf[j][0] = Bs[k0 + t][n0 + g];
                bf[j][1] = Bs[k0 + t + 4][n0 + g];
            }
#pragma unroll
            for (int i = 0; i < 4; i++)
#pragma unroll
                for (int j = 0; j < 4; j++)
                    mma_tf32(acc[i][j], af[i], bf[j]);
        }
    }

#pragma unroll
    for (int i = 0; i < 4; i++) {
#pragma unroll
        for (int j = 0; j < 4; j++) {
            int col = bn + warpN * 32 + j * 8 + t * 2;
#pragma unroll
            for (int half = 0; half < 2; half++) {
                int m = bm + warpM * 64 + i * 16 + g + half * 8;
                float2 v = half == 0 ? make_float2(acc[i][j][0], acc[i][j][1])
                                     : make_float2(acc[i][j][2], acc[i][j][3]);
                if (MODE == 2) {
                    *(float2*)(Cout + (size_t)m * N + col) = v;
                } else {
                    int b = m >> 11;
                    int tt = m & (TT - 1);
                    if (MODE == 0) {
                        if (col < TC) {
                            int bh = b * NH + (col >> 6);
                            int dd = col & 63;
                            store_q(bh, tt, dd, v.x);
                            store_q(bh, tt, dd + 1, v.y);
                        } else {
                            int nn = col - TC;
                            int bh = b * NH + (nn >> 6);
                            int dd = nn & 63;
                            store_kfrag(g_kh, g_kl, bh, tt, dd, v.x);
                            store_kfrag(g_kh, g_kl, bh, tt, dd + 1, v.y);
                        }
                    } else {
                        int bh = b * NH + (col >> 6);
                        int dd = col & 63;
                        float ka0 = 1.f / (1.f + __expf(-0.0025f * v.x));
                        float ka1 = 1.f / (1.f + __expf(-0.0025f * v.y));
                        store_kfrag(g_kah, g_kal, bh, tt, dd, ka0);
                        store_kfrag(g_kah, g_kal, bh, tt, dd + 1, ka1);
                    }
                }
            }
        }
    }
}

// ---------------------------------------------------------------------------
// Fused tensor-core attention, 256 threads (8 warps), 64x64 tiles, round-5
// loop shape, frag-major smem (wide conflict-free LDS.64/LDS.128 gathers).
// Warp (wm, wn): q-rows [wm*16,+16), s-cols [wn*32,+32).
// smem: Qh,Ql,Kh,Kl,Vv each 4096 words = 81920 B -> 2 CTAs/SM.
// ---------------------------------------------------------------------------
template<int ARMA>
__global__ __launch_bounds__(256)
void fattn_kernel(const float* __restrict__ x)
{
    extern __shared__ uint32_t smu[];
    uint32_t* Qh = smu;            // 4 q-blocks * 1024
    uint32_t* Ql = Qh + 4096;
    uint32_t* Kh = Ql + 4096;      // 8 s-blocks * 512
    uint32_t* Kl = Kh + 4096;
    uint32_t* Vv = Kl + 4096;

    const int tid = threadIdx.x;
    const int lane = tid & 31;
    const int warp = tid >> 5;
    const int wm = warp >> 1;
    const int wn = warp & 1;
    const int g = lane >> 2;
    const int t = lane & 3;

    const int bh = blockIdx.y;
    const int b = bh >> 4, h = bh & 15;
    const int qb = (int)gridDim.x - 1 - (int)blockIdx.x;  // heavy first
    const int q0 = qb * 64;

    const size_t bhoff = (size_t)bh * (TT * 64);
    const uint32_t* qh_g = (ARMA ? g_qah : g_qsh) + bhoff;
    const uint32_t* ql_g = (ARMA ? g_qal : g_qsl) + bhoff;
    const uint32_t* kh_g = (ARMA ? g_kah : g_kh) + bhoff;
    const uint32_t* kl_g = (ARMA ? g_kal : g_kl) + bhoff;
    const uint32_t* v_g  = (ARMA ? g_e32 : g_v32) + bhoff;
    const float* yb = g_y + (size_t)bh * TT * HD;
    const float* vx = x + (size_t)b * TT * TC + h * HD;

    const uint32_t Qh_s = s2u(Qh), Ql_s = s2u(Ql);
    const uint32_t Kh_s = s2u(Kh), Kl_s = s2u(Kl), Vv_s = s2u(Vv);

    // ---- stage Q tile (4096 words hi + 4096 lo), identity copy
    {
        const uint32_t* qhT = qh_g + (size_t)q0 * 64;
        const uint32_t* qlT = ql_g + (size_t)q0 * 64;
#pragma unroll
        for (int k = 0; k < 4; k++) {
            cp_async16(Qh_s + (tid + k * 256) * 16, qhT + (size_t)(tid + k * 256) * 4);
            cp_async16(Ql_s + (tid + k * 256) * 16, qlT + (size_t)(tid + k * 256) * 4);
        }
    }

    float O[8][4];
#pragma unroll
    for (int n = 0; n < 8; n++)
#pragma unroll
        for (int c = 0; c < 4; c++) O[n][c] = 0.f;
    float m_run[2] = {-1e30f, -1e30f};
    float l_run[2] = {0.f, 0.f};

    const int qrow0 = q0 + wm * 16 + g;
    const int qrow1 = qrow0 + 8;
    const int sw = wn * 32;

    for (int kt = 0; kt <= qb; kt++) {
        const int s0 = kt * 64;
        __syncthreads();   // previous tile's readers done

        // ---- stage K hi/lo + V (identity copies, 4096 words each)
        {
            const uint32_t* khT = kh_g + (size_t)s0 * 64;
            const uint32_t* klT = kl_g + (size_t)s0 * 64;
            const uint32_t* vT  = v_g  + (size_t)s0 * 64;
#pragma unroll
            for (int k = 0; k < 4; k++) {
                int o = tid + k * 256;
                cp_async16(Kh_s + o * 16, khT + (size_t)o * 4);
                cp_async16(Kl_s + o * 16, klT + (size_t)o * 4);
                cp_async16(Vv_s + o * 16, vT + (size_t)o * 4);
            }
        }
        CP_COMMIT();
        CP_WAIT0();
        __syncthreads();

        // ---- S = Q @ K^T over this warp's 32 s-cols (3xTF32)
        float acc[4][4];
#pragma unroll
        for (int nb = 0; nb < 4; nb++)
#pragma unroll
            for (int c = 0; c < 4; c++) acc[nb][c] = 0.f;

#pragma unroll
        for (int c = 0; c < 8; c++) {           // k0 = 8c
            int qoff = wm * 1024 + lane * 32 + ((c + (lane & 7)) & 7) * 4;
            uint4 ahv = *(const uint4*)(Qh + qoff);
            uint4 alv = *(const uint4*)(Ql + qoff);
            uint32_t ah[4] = {ahv.x, ahv.y, ahv.z, ahv.w};
            uint32_t al[4] = {alv.x, alv.y, alv.z, alv.w};
#pragma unroll
            for (int nb = 0; nb < 4; nb++) {
                int koff = (wn * 4 + nb) * 512 + lane * 16
                         + ((c + (lane >> 1)) & 7) * 2;
                uint2 kh2 = *(const uint2*)(Kh + koff);
                uint2 kl2 = *(const uint2*)(Kl + koff);
                uint32_t bh2[2] = {kh2.x, kh2.y};
                uint32_t bl2[2] = {kl2.x, kl2.y};
                mma_tf32(acc[nb], ah, bh2);
                mma_tf32(acc[nb], al, bh2);
                mma_tf32(acc[nb], ah, bl2);
            }
        }

        const bool diag = (kt == qb);
        if (diag) {
#pragma unroll
            for (int nb = 0; nb < 4; nb++) {
                int colb = s0 + sw + nb * 8 + 2 * t;
#pragma unroll
                for (int c = 0; c < 4; c++) {
                    int cc = colb + (c & 1);
                    int rr = (c >= 2) ? qrow1 : qrow0;
                    if (ARMA) { if (cc >= rr) acc[nb][c] = 0.f; }
                    else      { if (cc >  rr) acc[nb][c] = -1e30f; }
                }
            }
        }

        if (!ARMA) {
            float mt0 = -1e30f, mt1 = -1e30f;
#pragma unroll
            for (int nb = 0; nb < 4; nb++) {
                mt0 = fmaxf(mt0, fmaxf(acc[nb][0], acc[nb][1]));
                mt1 = fmaxf(mt1, fmaxf(acc[nb][2], acc[nb][3]));
            }
#pragma unroll
            for (int off = 1; off <= 2; off <<= 1) {
                mt0 = fmaxf(mt0, __shfl_xor_sync(0xffffffffu, mt0, off));
                mt1 = fmaxf(mt1, __shfl_xor_sync(0xffffffffu, mt1, off));
            }
            float mn0 = fmaxf(m_run[0], mt0);
            float mn1 = fmaxf(m_run[1], mt1);
            float corr0 = __expf(m_run[0] - mn0);
            float corr1 = __expf(m_run[1] - mn1);
            m_run[0] = mn0; m_run[1] = mn1;

            float ls0 = 0.f, ls1 = 0.f;
#pragma unroll
            for (int nb = 0; nb < 4; nb++) {
                float p0 = __expf(acc[nb][0] - mn0);
                float p1 = __expf(acc[nb][1] - mn0);
                float p2 = __expf(acc[nb][2] - mn1);
                float p3 = __expf(acc[nb][3] - mn1);
                if (diag) {
                    int colb = s0 + sw + nb * 8 + 2 * t;
                    if (colb     > qrow0) p0 = 0.f;
                    if (colb + 1 > qrow0) p1 = 0.f;
                    if (colb     > qrow1) p2 = 0.f;
                    if (colb + 1 > qrow1) p3 = 0.f;
                }
                acc[nb][0] = p0; acc[nb][1] = p1;
                acc[nb][2] = p2; acc[nb][3] = p3;
                ls0 += p0 + p1;
                ls1 += p2 + p3;
            }
#pragma unroll
            for (int off = 1; off <= 2; off <<= 1) {
                ls0 += __shfl_xor_sync(0xffffffffu, ls0, off);
                ls1 += __shfl_xor_sync(0xffffffffu, ls1, off);
            }
            l_run[0] = l_run[0] * corr0 + ls0;
            l_run[1] = l_run[1] * corr1 + ls1;
#pragma unroll
            for (int n = 0; n < 8; n++) {
                O[n][0] *= corr0; O[n][1] *= corr0;
                O[n][2] *= corr1; O[n][3] *= corr1;
            }
        }

        // ---- O += P @ V : P via shfl; V via 4 LDS.128 per nb
#pragma unroll
        for (int nb = 0; nb < 4; nb++) {
            int src0 = (lane & ~3) | (t >> 1);
            int src2 = src0 + 2;
            float s00 = __shfl_sync(0xffffffffu, acc[nb][0], src0);
            float s01 = __shfl_sync(0xffffffffu, acc[nb][1], src0);
            float s20 = __shfl_sync(0xffffffffu, acc[nb][0], src2);
            float s21 = __shfl_sync(0xffffffffu, acc[nb][1], src2);
            float s10 = __shfl_sync(0xffffffffu, acc[nb][2], src0);
            float s11 = __shfl_sync(0xffffffffu, acc[nb][3], src0);
            float s30 = __shfl_sync(0xffffffffu, acc[nb][2], src2);
            float s31 = __shfl_sync(0xffffffffu, acc[nb][3], src2);
            bool odd = (t & 1);
            float pa0 = odd ? s01 : s00;
            float pa1 = odd ? s11 : s10;
            float pa2 = odd ? s21 : s20;
            float pa3 = odd ? s31 : s30;
            uint32_t ah[4], al[4];
            split_tf32(pa0, ah[0], al[0]);
            split_tf32(pa1, ah[1], al[1]);
            split_tf32(pa2, ah[2], al[2]);
            split_tf32(pa3, ah[3], al[3]);

            int vb = (wn * 4 + nb) * 512 + lane * 16;
            uint32_t vfr[16];
#pragma unroll
            for (int G = 0; G < 4; G++) {
                uint4 t4 = *(const uint4*)(Vv + vb + ((G + (lane >> 1)) & 3) * 4);
                vfr[G * 4 + 0] = t4.x; vfr[G * 4 + 1] = t4.y;
                vfr[G * 4 + 2] = t4.z; vfr[G * 4 + 3] = t4.w;
            }
#pragma unroll
            for (int n = 0; n < 8; n++) {
                uint32_t bv[2] = {vfr[n], vfr[8 + n]};
                mma_tf32(O[n], ah, bv);
                mma_tf32(O[n], al, bv);
            }
        }
    }

    // ---- merge the two wn stripes once, write out
    __syncthreads();
    const int r0l = wm * 16 + g, r1l = r0l + 8;
    float* Ob = (float*)Qh;        // reuse Qh+Ql (8192 words), pitch 66
    if (!ARMA) {
        float* ml = (float*)Kh;
        if (t == 0) {
            ml[r0l * 4 + wn * 2 + 0] = m_run[0];
            ml[r0l * 4 + wn * 2 + 1] = l_run[0];
            ml[r1l * 4 + wn * 2 + 0] = m_run[1];
            ml[r1l * 4 + wn * 2 + 1] = l_run[1];
        }
        __syncthreads();
        float ma0 = ml[r0l * 4 + 0], la0 = ml[r0l * 4 + 1];
        float mb0 = ml[r0l * 4 + 2], lb0 = ml[r0l * 4 + 3];
        float ma1 = ml[r1l * 4 + 0], la1 = ml[r1l * 4 + 1];
        float mb1 = ml[r1l * 4 + 2], lb1 = ml[r1l * 4 + 3];
        float mm0 = fmaxf(ma0, mb0), mm1 = fmaxf(ma1, mb1);
        float lt0 = la0 * __expf(ma0 - mm0) + lb0 * __expf(mb0 - mm0);
        float lt1 = la1 * __expf(ma1 - mm1) + lb1 * __expf(mb1 - mm1);
        float f0 = __expf(m_run[0] - mm0);
        float f1 = __expf(m_run[1] - mm1);
#pragma unroll
        for (int n = 0; n < 8; n++) {
            O[n][0] *= f0; O[n][1] *= f0;
            O[n][2] *= f1; O[n][3] *= f1;
        }
        if (wn == 1) {
#pragma unroll
            for (int n = 0; n < 8; n++) {
                int col = n * 8 + 2 * t;
                *(float2*)(Ob + r0l * 66 + col) = make_float2(O[n][0], O[n][1]);
                *(float2*)(Ob + r1l * 66 + col) = make_float2(O[n][2], O[n][3]);
            }
        }
        __syncthreads();
        if (wn == 0) {
            float inv0 = 1.f / lt0, inv1 = 1.f / lt1;
            float* yo = g_y + (size_t)bh * TT * HD;
            uint32_t* eo = g_e32 + bhoff;
#pragma unroll
            for (int n = 0; n < 8; n++) {
                int col = n * 8 + 2 * t;
                float2 p0 = *(const float2*)(Ob + r0l * 66 + col);
                float2 p1 = *(const float2*)(Ob + r1l * 66 + col);
                float y00 = (O[n][0] + p0.x) * inv0;
                float y01 = (O[n][1] + p0.y) * inv0;
                float y10 = (O[n][2] + p1.x) * inv1;
                float y11 = (O[n][3] + p1.y) * inv1;
                *(float2*)(yo + (size_t)qrow0 * HD + col) = make_float2(y00, y01);
                *(float2*)(yo + (size_t)qrow1 * HD + col) = make_float2(y10, y11);
                float e00 = 0.f, e01 = 0.f, e10 = 0.f, e11 = 0.f;
                if (qrow0 + 1 < TT) {
                    float2 xv = *(const float2*)(vx + (size_t)(qrow0 + 1) * TC + col);
                    e00 = xv.x - y00; e01 = xv.y - y01;
                }
                if (qrow1 + 1 < TT) {
                    float2 xv = *(const float2*)(vx + (size_t)(qrow1 + 1) * TC + col);
                    e10 = xv.x - y10; e11 = xv.y - y11;
                }
                eo[vfrag_idx(qrow0, col)]     = f2tf32(e00);
                eo[vfrag_idx(qrow0, col + 1)] = f2tf32(e01);
                eo[vfrag_idx(qrow1, col)]     = f2tf32(e10);
                eo[vfrag_idx(qrow1, col + 1)] = f2tf32(e11);
            }
        }
    } else {
        if (wn == 1) {
#pragma unroll
            for (int n = 0; n < 8; n++) {
                int col = n * 8 + 2 * t;
                *(float2*)(Ob + r0l * 66 + col) = make_float2(O[n][0], O[n][1]);
                *(float2*)(Ob + r1l * 66 + col) = make_float2(O[n][2], O[n][3]);
            }
        }
        __syncthreads();
        if (wn == 0) {
            float* yo = g_ysum + (size_t)b * TT * TC + h * HD;
#pragma unroll
            for (int n = 0; n < 8; n++) {
                int col = n * 8 + 2 * t;
                float2 p0 = *(const float2*)(Ob + r0l * 66 + col);
                float2 p1 = *(const float2*)(Ob + r1l * 66 + col);
                float2 y0 = *(const float2*)(yb + (size_t)qrow0 * HD + col);
                float2 y1 = *(const float2*)(yb + (size_t)qrow1 * HD + col);
                *(float2*)(yo + (size_t)qrow0 * TC + col) =
                    make_float2(O[n][0] + p0.x + y0.x, O[n][1] + p0.y + y0.y);
                *(float2*)(yo + (size_t)qrow1 * TC + col) =
                    make_float2(O[n][2] + p1.x + y1.x, O[n][3] + p1.y + y1.y);
            }
        }
    }
}

// ---------------------------------------------------------------------------
extern "C" void kernel_launch(void* const* d_in, const int* in_sizes, int n_in,
                              void* d_out, int out_size)
{
    (void)in_sizes; (void)n_in; (void)out_size;
    const float* x      = (const float*)d_in[0];
    const float* W_attn = (const float*)d_in[1];
    const float* W_k2   = (const float*)d_in[2];
    const float* W_proj = (const float*)d_in[3];
    float* out = (float*)d_out;

    const int smem_attn = 5 * 4096 * (int)sizeof(uint32_t);  // 81920 B
    cudaFuncSetAttribute(fattn_kernel<0>,
                         cudaFuncAttributeMaxDynamicSharedMemorySize, smem_attn);
    cudaFuncSetAttribute(fattn_kernel<1>,
                         cudaFuncAttributeMaxDynamicSharedMemorySize, smem_attn);

    dim3 blk(256);
    prep_v32_kernel<<<(int)(NELEM / 4 / 256), 256>>>(x);
    tgemm_kernel<0><<<dim3(2 * TC / 128, MROWS / 128), blk>>>(
        x, W_attn, nullptr, MROWS, 2 * TC, TC);
    tgemm_kernel<1><<<dim3(TC / 128, MROWS / 128), blk>>>(
        x, W_k2, nullptr, MROWS, TC, TC);
    fattn_kernel<0><<<dim3(TT / 64, BHN), 256, smem_attn>>>(x);
    fattn_kernel<1><<<dim3(TT / 64, BHN), 256, smem_attn>>>(x);
    tgemm_kernel<2><<<dim3(TC / 128, MROWS / 128), blk>>>(
        nullptr, W_proj, out, MROWS, TC, TC);
}

// round 8
// speedup vs baseline: 1.2320x; 1.0929x over previous
#include <cuda_runtime.h>
#include <math.h>
#include <stdint.h>

#define TB 2
#define TT 2048
#define TC 1024
#define NH 16
#define HD 64
#define BHN (TB*NH)
#define MROWS (TB*TT)
#define SCALE 0.125f

#define NELEM ((size_t)BHN*TT*HD)

// Frag-major attention operands (tf32 words)
__device__ __align__(16) uint32_t g_qsh[NELEM], g_qsl[NELEM];  // q*scale hi/lo
__device__ __align__(16) uint32_t g_kfr[2*NELEM];   // k hi/lo interleaved uint4
__device__ __align__(16) uint32_t g_kafr[2*NELEM];  // ka hi/lo interleaved
__device__ __align__(16) uint32_t g_v32[NELEM];     // tf32(x) V-frag layout
__device__ __align__(16) uint32_t g_e32[NELEM];     // tf32(x[s+1]-y[s])
__device__ __align__(16) float    g_y[NELEM];
// tf32 GEMM operands (pre-converted once)
__device__ __align__(16) uint32_t g_xt[(size_t)MROWS*TC];
__device__ __align__(16) uint32_t g_wat[(size_t)TC*2*TC];
__device__ __align__(16) uint32_t g_wk2[(size_t)TC*TC];
__device__ __align__(16) uint32_t g_wpr[(size_t)TC*TC];
__device__ __align__(16) uint32_t g_ysumt[(size_t)TB*TT*TC];

__device__ __forceinline__ uint32_t f2tf32(float f) {
    uint32_t u;
    asm volatile("cvt.rna.tf32.f32 %0, %1;" : "=r"(u) : "f"(f));
    return u;
}
__device__ __forceinline__ void split_tf32(float v, uint32_t& hi, uint32_t& lo) {
    hi = f2tf32(v);
    lo = f2tf32(v - __uint_as_float(hi));
}
__device__ __forceinline__ void mma_tf32(float c[4], const uint32_t a[4],
                                         const uint32_t b[2]) {
    asm volatile(
        "mma.sync.aligned.m16n8k8.row.col.f32.tf32.tf32.f32 "
        "{%0,%1,%2,%3}, {%4,%5,%6,%7}, {%8,%9}, {%0,%1,%2,%3};"
        : "+f"(c[0]), "+f"(c[1]), "+f"(c[2]), "+f"(c[3])
        : "r"(a[0]), "r"(a[1]), "r"(a[2]), "r"(a[3]), "r"(b[0]), "r"(b[1]));
}
__device__ __forceinline__ uint32_t s2u(const void* p) {
    return (uint32_t)__cvta_generic_to_shared(p);
}
__device__ __forceinline__ void cp_async16(uint32_t dst, const void* src) {
    asm volatile("cp.async.cg.shared.global [%0], [%1], 16;"
                 :: "r"(dst), "l"(src));
}
#define CP_COMMIT() asm volatile("cp.async.commit_group;")
#define CP_WAIT0()  asm volatile("cp.async.wait_group 0;" ::: "memory")
#define CP_WAIT1()  asm volatile("cp.async.wait_group 1;" ::: "memory")

// ---- frag-layout index helpers ----
__device__ __forceinline__ size_t qfrag_idx(int tt, int dd) {
    int lane = ((tt & 7) << 2) | (dd & 3);
    int word = (((dd >> 3) + (lane & 7)) & 7) * 4
             + ((tt >> 3) & 1) + (((dd >> 2) & 1) << 1);
    return ((size_t)(tt >> 4)) * 1024 + lane * 32 + word;
}
// K interleaved: per 8-row block 1024 words; uint4 = [h0,h1,l0,l1]
__device__ __forceinline__ size_t kfr_idx(int s, int d) {
    int lane = ((s & 7) << 2) | (d & 3);
    int word = (((d >> 3) + (lane & 7)) & 7) * 4 + ((d >> 2) & 1);
    return ((size_t)(s >> 3)) * 1024 + lane * 32 + word;
}
__device__ __forceinline__ size_t vfrag_idx(int s, int d) {
    int lane = ((d & 7) << 2) | (s & 3);
    int n = d >> 3;
    int grp = ((s >> 2) & 1) * 2 + (n >> 2);
    int word = ((grp + (lane >> 1)) & 3) * 4 + (n & 3);
    return ((size_t)(s >> 3)) * 512 + lane * 16 + word;
}
__device__ __forceinline__ void store_q(int bh, int tt, int dd, float qraw) {
    float qs = qraw * SCALE;
    size_t f = (size_t)bh * (TT * 64) + qfrag_idx(tt, dd);
    uint32_t h, l;
    split_tf32(qs, h, l);
    g_qsh[f] = h; g_qsl[f] = l;
}
__device__ __forceinline__ void store_kfr(uint32_t* arr, int bh, int tt,
                                          int dd, float v) {
    size_t f = (size_t)bh * (TT * 128) + kfr_idx(tt, dd);
    uint32_t h, l;
    split_tf32(v, h, l);
    arr[f] = h; arr[f + 2] = l;
}

// ---------------------------------------------------------------------------
// conv: fp32 -> tf32 word arrays (once per launch)
// W: 0=x->g_xt, 1=W_attn->g_wat, 2=W_k2->g_wk2, 3=W_proj->g_wpr
// ---------------------------------------------------------------------------
template<int W>
__global__ __launch_bounds__(256)
void conv_tf32_kernel(const float* __restrict__ src)
{
    uint32_t* dst = (W == 0) ? g_xt : (W == 1) ? g_wat : (W == 2) ? g_wk2 : g_wpr;
    size_t i = (size_t)blockIdx.x * 256 + threadIdx.x;
    float4 v = ((const float4*)src)[i];
    ((uint4*)dst)[i] = make_uint4(f2tf32(v.x), f2tf32(v.y), f2tf32(v.z), f2tf32(v.w));
}

// ---------------------------------------------------------------------------
// prep: v32 = tf32(x) into V-frag layout via smem bounce (coalesced both ways)
// ---------------------------------------------------------------------------
__global__ __launch_bounds__(256)
void prep_v32_kernel(const float* __restrict__ x)
{
    __shared__ uint32_t vs[4096];
    const int tid = threadIdx.x;
    const int bh = blockIdx.y;
    const int s0 = blockIdx.x * 64;
    const int b = bh >> 4, h = bh & 15;
    const int lr = tid >> 4, lc4 = (tid & 15) << 2;
#pragma unroll
    for (int it = 0; it < 4; it++) {
        int r = lr + it * 16;
        float4 v = *(const float4*)(x + ((size_t)b * TT + s0 + r) * TC + h * 64 + lc4);
        vs[vfrag_idx(r, lc4 + 0)] = f2tf32(v.x);
        vs[vfrag_idx(r, lc4 + 1)] = f2tf32(v.y);
        vs[vfrag_idx(r, lc4 + 2)] = f2tf32(v.z);
        vs[vfrag_idx(r, lc4 + 3)] = f2tf32(v.w);
    }
    __syncthreads();
    uint32_t* dst = g_v32 + (size_t)bh * (TT * 64) + (size_t)s0 * 64;
#pragma unroll
    for (int k = 0; k < 4; k++) {
        int o = (tid + k * 256) * 4;
        *(uint4*)(dst + o) = *(const uint4*)(vs + o);
    }
}

// ---------------------------------------------------------------------------
// TF32 GEMM, 3-stage cp.async pipeline, operands already tf32 (no CVT in loop)
// MODE 0: g_xt @ g_wat -> qs frags (n<TC) / kfr (n>=TC)
// MODE 1: g_xt @ g_wk2 -> kafr (sigmoid)
// MODE 2: g_ysumt @ g_wpr -> Cout
// smem: As [3][128][20] + Bs [3][16][136] = 56832 B dynamic
// ---------------------------------------------------------------------------
template<int MODE>
__global__ __launch_bounds__(256)
void tgemm_kernel(float* __restrict__ Cout, int M, int N, int K)
{
    extern __shared__ uint32_t smg[];
    const int tid = threadIdx.x;
    const int lane = tid & 31;
    const int warp = tid >> 5;
    const int warpM = warp >> 2, warpN = warp & 3;
    const int g = lane >> 2, t = lane & 3;
    const int bm = blockIdx.y * 128, bn = blockIdx.x * 128;

    const uint32_t* Ap = (MODE == 2) ? g_ysumt : g_xt;
    const uint32_t* Bw = (MODE == 0) ? g_wat : (MODE == 1) ? g_wk2 : g_wpr;

    float acc[4][4][4];
#pragma unroll
    for (int i = 0; i < 4; i++)
#pragma unroll
        for (int j = 0; j < 4; j++)
#pragma unroll
            for (int r = 0; r < 4; r++) acc[i][j][r] = 0.f;

    auto issue = [&](int kt, int st) {
#pragma unroll
        for (int l = 0; l < 2; l++) {
            int id = tid + l * 256;
            int ar = id >> 2, ak = (id & 3) << 2;
            cp_async16(s2u(smg + st * 2560 + ar * 20 + ak),
                       Ap + (size_t)(bm + ar) * K + kt + ak);
            int br = id >> 5, bc = (id & 31) << 2;
            cp_async16(s2u(smg + 7680 + st * 2176 + br * 136 + bc),
                       Bw + (size_t)(kt + br) * N + bn + bc);
        }
        CP_COMMIT();
    };

    issue(0, 0);
    issue(16, 1);
    const int nk = K >> 4;

    for (int i = 0; i < nk; i++) {
        const int st = i % 3;
        const uint32_t* Asb = smg + st * 2560;
        const uint32_t* Bsb = smg + 7680 + st * 2176;
        if (i + 1 < nk) { CP_WAIT1(); } else { CP_WAIT0(); }
        __syncthreads();
#pragma unroll
        for (int ks = 0; ks < 2; ks++) {
            const int k0 = ks * 8;
            uint32_t af[4][4], bf[4][2];
#pragma unroll
            for (int i4 = 0; i4 < 4; i4++) {
                int m0 = warpM * 64 + i4 * 16;
                af[i4][0] = Asb[(m0 + g) * 20 + k0 + t];
                af[i4][1] = Asb[(m0 + g + 8) * 20 + k0 + t];
                af[i4][2] = Asb[(m0 + g) * 20 + k0 + t + 4];
                af[i4][3] = Asb[(m0 + g + 8) * 20 + k0 + t + 4];
            }
#pragma unroll
            for (int j = 0; j < 4; j++) {
                int n0 = warpN * 32 + j * 8;
                bf[j][0] = Bsb[(k0 + t) * 136 + n0 + g];
                bf[j][1] = Bsb[(k0 + t + 4) * 136 + n0 + g];
            }
#pragma unroll
            for (int i4 = 0; i4 < 4; i4++)
#pragma unroll
                for (int j = 0; j < 4; j++)
                    mma_tf32(acc[i4][j], af[i4], bf[j]);
        }
        if (i + 2 < nk) issue((i + 2) << 4, (i + 2) % 3);
    }

    // epilogue
#pragma unroll
    for (int i = 0; i < 4; i++) {
#pragma unroll
        for (int j = 0; j < 4; j++) {
            int col = bn + warpN * 32 + j * 8 + t * 2;
#pragma unroll
            for (int half = 0; half < 2; half++) {
                int m = bm + warpM * 64 + i * 16 + g + half * 8;
                float2 v = half == 0 ? make_float2(acc[i][j][0], acc[i][j][1])
                                     : make_float2(acc[i][j][2], acc[i][j][3]);
                if (MODE == 2) {
                    *(float2*)(Cout + (size_t)m * N + col) = v;
                } else {
                    int b = m >> 11;
                    int tt = m & (TT - 1);
                    if (MODE == 0) {
                        if (col < TC) {
                            int bh = b * NH + (col >> 6);
                            int dd = col & 63;
                            store_q(bh, tt, dd, v.x);
                            store_q(bh, tt, dd + 1, v.y);
                        } else {
                            int nn = col - TC;
                            int bh = b * NH + (nn >> 6);
                            int dd = nn & 63;
                            store_kfr(g_kfr, bh, tt, dd, v.x);
                            store_kfr(g_kfr, bh, tt, dd + 1, v.y);
                        }
                    } else {
                        int bh = b * NH + (col >> 6);
                        int dd = col & 63;
                        float ka0 = 1.f / (1.f + __expf(-0.0025f * v.x));
                        float ka1 = 1.f / (1.f + __expf(-0.0025f * v.y));
                        store_kfr(g_kafr, bh, tt, dd, ka0);
                        store_kfr(g_kafr, bh, tt, dd + 1, ka1);
                    }
                }
            }
        }
    }
}

// ---------------------------------------------------------------------------
// Fused tensor-core attention, 256 threads (8 warps), 64x64 tiles.
// K hi/lo interleaved -> one LDS.128 per (c,nb). ARMA=1 derives qa from qs
// at Q staging (once per CTA). smem: Qh,Ql(8192) + Kf(8192) + Vv(4096)
// = 20480 words = 81920 B -> 2 CTAs/SM.
// ---------------------------------------------------------------------------
template<int ARMA>
__global__ __launch_bounds__(256)
void fattn_kernel(const float* __restrict__ x)
{
    extern __shared__ uint32_t smu[];
    uint32_t* Qh = smu;
    uint32_t* Ql = Qh + 4096;
    uint32_t* Kf = Ql + 4096;      // 8 s-blocks * 1024 (hi/lo interleaved)
    uint32_t* Vv = Kf + 8192;

    const int tid = threadIdx.x;
    const int lane = tid & 31;
    const int warp = tid >> 5;
    const int wm = warp >> 1;
    const int wn = warp & 1;
    const int g = lane >> 2;
    const int t = lane & 3;

    const int bh = blockIdx.y;
    const int b = bh >> 4, h = bh & 15;
    const int qb = (int)gridDim.x - 1 - (int)blockIdx.x;  // heavy first
    const int q0 = qb * 64;

    const size_t bhoff = (size_t)bh * (TT * 64);
    const uint32_t* kf_g = (ARMA ? g_kafr : g_kfr) + (size_t)bh * (TT * 128);
    const uint32_t* v_g  = (ARMA ? g_e32 : g_v32) + bhoff;
    const float* yb = g_y + (size_t)bh * TT * HD;
    const float* vx = x + (size_t)b * TT * TC + h * HD;

    const uint32_t Qh_s = s2u(Qh), Ql_s = s2u(Ql);
    const uint32_t Kf_s = s2u(Kf), Vv_s = s2u(Vv);

    // ---- stage Q
    if (ARMA) {
        // reconstruct qs, apply leaky-min, re-split (once per CTA)
        const uint32_t* qhT = g_qsh + bhoff + (size_t)q0 * 64;
        const uint32_t* qlT = g_qsl + bhoff + (size_t)q0 * 64;
#pragma unroll
        for (int k = 0; k < 4; k++) {
            int o = (tid + k * 256) * 4;
            uint4 hv = *(const uint4*)(qhT + o);
            uint4 lv = *(const uint4*)(qlT + o);
            uint32_t oh[4], ol[4];
            float qs, qa;
            qs = __uint_as_float(hv.x) + __uint_as_float(lv.x);
            qa = fminf(qs, 0.02f * qs); split_tf32(qa, oh[0], ol[0]);
            qs = __uint_as_float(hv.y) + __uint_as_float(lv.y);
            qa = fminf(qs, 0.02f * qs); split_tf32(qa, oh[1], ol[1]);
            qs = __uint_as_float(hv.z) + __uint_as_float(lv.z);
            qa = fminf(qs, 0.02f * qs); split_tf32(qa, oh[2], ol[2]);
            qs = __uint_as_float(hv.w) + __uint_as_float(lv.w);
            qa = fminf(qs, 0.02f * qs); split_tf32(qa, oh[3], ol[3]);
            *(uint4*)(Qh + o) = make_uint4(oh[0], oh[1], oh[2], oh[3]);
            *(uint4*)(Ql + o) = make_uint4(ol[0], ol[1], ol[2], ol[3]);
        }
    } else {
        const uint32_t* qhT = g_qsh + bhoff + (size_t)q0 * 64;
        const uint32_t* qlT = g_qsl + bhoff + (size_t)q0 * 64;
#pragma unroll
        for (int k = 0; k < 4; k++) {
            int o = (tid + k * 256) * 4;
            cp_async16(Qh_s + o * 4, qhT + o);
            cp_async16(Ql_s + o * 4, qlT + o);
        }
    }

    float O[8][4];
#pragma unroll
    for (int n = 0; n < 8; n++)
#pragma unroll
        for (int c = 0; c < 4; c++) O[n][c] = 0.f;
    float m_run[2] = {-1e30f, -1e30f};
    float l_run[2] = {0.f, 0.f};

    const int qrow0 = q0 + wm * 16 + g;
    const int qrow1 = qrow0 + 8;
    const int sw = wn * 32;

    for (int kt = 0; kt <= qb; kt++) {
        const int s0 = kt * 64;
        __syncthreads();   // previous tile's readers done

        // ---- stage K (interleaved hi/lo) + V, identity copies
        {
            const uint32_t* kT = kf_g + (size_t)s0 * 128;
            const uint32_t* vT = v_g + (size_t)s0 * 64;
#pragma unroll
            for (int k = 0; k < 8; k++) {
                int o = (tid + k * 256) * 4;
                cp_async16(Kf_s + o * 4, kT + o);
            }
#pragma unroll
            for (int k = 0; k < 4; k++) {
                int o = (tid + k * 256) * 4;
                cp_async16(Vv_s + o * 4, vT + o);
            }
        }
        CP_COMMIT();
        CP_WAIT0();
        __syncthreads();

        // ---- S = Q @ K^T over this warp's 32 s-cols (3xTF32)
        float acc[4][4];
#pragma unroll
        for (int nb = 0; nb < 4; nb++)
#pragma unroll
            for (int c = 0; c < 4; c++) acc[nb][c] = 0.f;

#pragma unroll
        for (int c = 0; c < 8; c++) {
            int qoff = wm * 1024 + lane * 32 + ((c + (lane & 7)) & 7) * 4;
            uint4 ahv = *(const uint4*)(Qh + qoff);
            uint4 alv = *(const uint4*)(Ql + qoff);
            uint32_t ah[4] = {ahv.x, ahv.y, ahv.z, ahv.w};
            uint32_t al[4] = {alv.x, alv.y, alv.z, alv.w};
#pragma unroll
            for (int nb = 0; nb < 4; nb++) {
                int koff = (wn * 4 + nb) * 1024 + lane * 32
                         + ((c + (lane & 7)) & 7) * 4;
                uint4 kk = *(const uint4*)(Kf + koff);
                uint32_t bh2[2] = {kk.x, kk.y};
                uint32_t bl2[2] = {kk.z, kk.w};
                mma_tf32(acc[nb], ah, bh2);
                mma_tf32(acc[nb], al, bh2);
                mma_tf32(acc[nb], ah, bl2);
            }
        }

        const bool diag = (kt == qb);
        if (diag) {
#pragma unroll
            for (int nb = 0; nb < 4; nb++) {
                int colb = s0 + sw + nb * 8 + 2 * t;
#pragma unroll
                for (int c = 0; c < 4; c++) {
                    int cc = colb + (c & 1);
                    int rr = (c >= 2) ? qrow1 : qrow0;
                    if (ARMA) { if (cc >= rr) acc[nb][c] = 0.f; }
                    else      { if (cc >  rr) acc[nb][c] = -1e30f; }
                }
            }
        }

        if (!ARMA) {
            float mt0 = -1e30f, mt1 = -1e30f;
#pragma unroll
            for (int nb = 0; nb < 4; nb++) {
                mt0 = fmaxf(mt0, fmaxf(acc[nb][0], acc[nb][1]));
                mt1 = fmaxf(mt1, fmaxf(acc[nb][2], acc[nb][3]));
            }
#pragma unroll
            for (int off = 1; off <= 2; off <<= 1) {
                mt0 = fmaxf(mt0, __shfl_xor_sync(0xffffffffu, mt0, off));
                mt1 = fmaxf(mt1, __shfl_xor_sync(0xffffffffu, mt1, off));
            }
            float mn0 = fmaxf(m_run[0], mt0);
            float mn1 = fmaxf(m_run[1], mt1);
            float corr0 = __expf(m_run[0] - mn0);
            float corr1 = __expf(m_run[1] - mn1);
            m_run[0] = mn0; m_run[1] = mn1;

            float ls0 = 0.f, ls1 = 0.f;
#pragma unroll
            for (int nb = 0; nb < 4; nb++) {
                float p0 = __expf(acc[nb][0] - mn0);
                float p1 = __expf(acc[nb][1] - mn0);
                float p2 = __expf(acc[nb][2] - mn1);
                float p3 = __expf(acc[nb][3] - mn1);
                if (diag) {
                    int colb = s0 + sw + nb * 8 + 2 * t;
                    if (colb     > qrow0) p0 = 0.f;
                    if (colb + 1 > qrow0) p1 = 0.f;
                    if (colb     > qrow1) p2 = 0.f;
                    if (colb + 1 > qrow1) p3 = 0.f;
                }
                acc[nb][0] = p0; acc[nb][1] = p1;
                acc[nb][2] = p2; acc[nb][3] = p3;
                ls0 += p0 + p1;
                ls1 += p2 + p3;
            }
#pragma unroll
            for (int off = 1; off <= 2; off <<= 1) {
                ls0 += __shfl_xor_sync(0xffffffffu, ls0, off);
                ls1 += __shfl_xor_sync(0xffffffffu, ls1, off);
            }
            l_run[0] = l_run[0] * corr0 + ls0;
            l_run[1] = l_run[1] * corr1 + ls1;
#pragma unroll
            for (int n = 0; n < 8; n++) {
                O[n][0] *= corr0; O[n][1] *= corr0;
                O[n][2] *= corr1; O[n][3] *= corr1;
            }
        }

        // ---- O += P @ V : P via shfl; V via 4 LDS.128 per nb
#pragma unroll
        for (int nb = 0; nb < 4; nb++) {
            int src0 = (lane & ~3) | (t >> 1);
            int src2 = src0 + 2;
            float s00 = __shfl_sync(0xffffffffu, acc[nb][0], src0);
            float s01 = __shfl_sync(0xffffffffu, acc[nb][1], src0);
            float s20 = __shfl_sync(0xffffffffu, acc[nb][0], src2);
            float s21 = __shfl_sync(0xffffffffu, acc[nb][1], src2);
            float s10 = __shfl_sync(0xffffffffu, acc[nb][2], src0);
            float s11 = __shfl_sync(0xffffffffu, acc[nb][3], src0);
            float s30 = __shfl_sync(0xffffffffu, acc[nb][2], src2);
            float s31 = __shfl_sync(0xffffffffu, acc[nb][3], src2);
            bool odd = (t & 1);
            float pa0 = odd ? s01 : s00;
            float pa1 = odd ? s11 : s10;
            float pa2 = odd ? s21 : s20;
            float pa3 = odd ? s31 : s30;
            uint32_t ah[4], al[4];
            split_tf32(pa0, ah[0], al[0]);
            split_tf32(pa1, ah[1], al[1]);
            split_tf32(pa2, ah[2], al[2]);
            split_tf32(pa3, ah[3], al[3]);

            int vb = (wn * 4 + nb) * 512 + lane * 16;
            uint32_t vfr[16];
#pragma unroll
            for (int G = 0; G < 4; G++) {
                uint4 t4 = *(const uint4*)(Vv + vb + ((G + (lane >> 1)) & 3) * 4);
                vfr[G * 4 + 0] = t4.x; vfr[G * 4 + 1] = t4.y;
                vfr[G * 4 + 2] = t4.z; vfr[G * 4 + 3] = t4.w;
            }
#pragma unroll
            for (int n = 0; n < 8; n++) {
                uint32_t bv[2] = {vfr[n], vfr[8 + n]};
                mma_tf32(O[n], ah, bv);
                mma_tf32(O[n], al, bv);
            }
        }
    }

    // ---- merge wn stripes, write out
    __syncthreads();
    const int r0l = wm * 16 + g, r1l = r0l + 8;
    float* Ob = (float*)Qh;        // reuse Qh+Ql (8192 words), pitch 66
    if (!ARMA) {
        float* ml = (float*)Kf;
        if (t == 0) {
            ml[r0l * 4 + wn * 2 + 0] = m_run[0];
            ml[r0l * 4 + wn * 2 + 1] = l_run[0];
            ml[r1l * 4 + wn * 2 + 0] = m_run[1];
            ml[r1l * 4 + wn * 2 + 1] = l_run[1];
        }
        __syncthreads();
        float ma0 = ml[r0l * 4 + 0], la0 = ml[r0l * 4 + 1];
        float mb0 = ml[r0l * 4 + 2], lb0 = ml[r0l * 4 + 3];
        float ma1 = ml[r1l * 4 + 0], la1 = ml[r1l * 4 + 1];
        float mb1 = ml[r1l * 4 + 2], lb1 = ml[r1l * 4 + 3];
        float mm0 = fmaxf(ma0, mb0), mm1 = fmaxf(ma1, mb1);
        float lt0 = la0 * __expf(ma0 - mm0) + lb0 * __expf(mb0 - mm0);
        float lt1 = la1 * __expf(ma1 - mm1) + lb1 * __expf(mb1 - mm1);
        float f0 = __expf(m_run[0] - mm0);
        float f1 = __expf(m_run[1] - mm1);
#pragma unroll
        for (int n = 0; n < 8; n++) {
            O[n][0] *= f0; O[n][1] *= f0;
            O[n][2] *= f1; O[n][3] *= f1;
        }
        if (wn == 1) {
#pragma unroll
            for (int n = 0; n < 8; n++) {
                int col = n * 8 + 2 * t;
                *(float2*)(Ob + r0l * 66 + col) = make_float2(O[n][0], O[n][1]);
                *(float2*)(Ob + r1l * 66 + col) = make_float2(O[n][2], O[n][3]);
            }
        }
        __syncthreads();
        if (wn == 0) {
            float inv0 = 1.f / lt0, inv1 = 1.f / lt1;
            float* yo = g_y + (size_t)bh * TT * HD;
            uint32_t* eo = g_e32 + bhoff;
#pragma unroll
            for (int n = 0; n < 8; n++) {
                int col = n * 8 + 2 * t;
                float2 p0 = *(const float2*)(Ob + r0l * 66 + col);
                float2 p1 = *(const float2*)(Ob + r1l * 66 + col);
                float y00 = (O[n][0] + p0.x) * inv0;
                float y01 = (O[n][1] + p0.y) * inv0;
                float y10 = (O[n][2] + p1.x) * inv1;
                float y11 = (O[n][3] + p1.y) * inv1;
                *(float2*)(yo + (size_t)qrow0 * HD + col) = make_float2(y00, y01);
                *(float2*)(yo + (size_t)qrow1 * HD + col) = make_float2(y10, y11);
                float e00 = 0.f, e01 = 0.f, e10 = 0.f, e11 = 0.f;
                if (qrow0 + 1 < TT) {
                    float2 xv = *(const float2*)(vx + (size_t)(qrow0 + 1) * TC + col);
                    e00 = xv.x - y00; e01 = xv.y - y01;
                }
                if (qrow1 + 1 < TT) {
                    float2 xv = *(const float2*)(vx + (size_t)(qrow1 + 1) * TC + col);
                    e10 = xv.x - y10; e11 = xv.y - y11;
                }
                eo[vfrag_idx(qrow0, col)]     = f2tf32(e00);
                eo[vfrag_idx(qrow0, col + 1)] = f2tf32(e01);
                eo[vfrag_idx(qrow1, col)]     = f2tf32(e10);
                eo[vfrag_idx(qrow1, col + 1)] = f2tf32(e11);
            }
        }
    } else {
        if (wn == 1) {
#pragma unroll
            for (int n = 0; n < 8; n++) {
                int col = n * 8 + 2 * t;
                *(float2*)(Ob + r0l * 66 + col) = make_float2(O[n][0], O[n][1]);
                *(float2*)(Ob + r1l * 66 + col) = make_float2(O[n][2], O[n][3]);
            }
        }
        __syncthreads();
        if (wn == 0) {
            uint32_t* yo = g_ysumt + (size_t)b * TT * TC + h * HD;
#pragma unroll
            for (int n = 0; n < 8; n++) {
                int col = n * 8 + 2 * t;
                float2 p0 = *(const float2*)(Ob + r0l * 66 + col);
                float2 p1 = *(const float2*)(Ob + r1l * 66 + col);
                float2 y0 = *(const float2*)(yb + (size_t)qrow0 * HD + col);
                float2 y1 = *(const float2*)(yb + (size_t)qrow1 * HD + col);
                *(uint2*)(yo + (size_t)qrow0 * TC + col) =
                    make_uint2(f2tf32(O[n][0] + p0.x + y0.x),
                               f2tf32(O[n][1] + p0.y + y0.y));
                *(uint2*)(yo + (size_t)qrow1 * TC + col) =
                    make_uint2(f2tf32(O[n][2] + p1.x + y1.x),
                               f2tf32(O[n][3] + p1.y + y1.y));
            }
        }
    }
}

// ---------------------------------------------------------------------------
extern "C" void kernel_launch(void* const* d_in, const int* in_sizes, int n_in,
                              void* d_out, int out_size)
{
    (void)in_sizes; (void)n_in; (void)out_size;
    const float* x      = (const float*)d_in[0];
    const float* W_attn = (const float*)d_in[1];
    const float* W_k2   = (const float*)d_in[2];
    const float* W_proj = (const float*)d_in[3];
    float* out = (float*)d_out;

    const int smem_attn = 20480 * (int)sizeof(uint32_t);  // 81920 B
    const int smem_gemm = (3 * 2560 + 3 * 2176) * (int)sizeof(uint32_t);  // 56832 B
    cudaFuncSetAttribute(fattn_kernel<0>,
                         cudaFuncAttributeMaxDynamicSharedMemorySize, smem_attn);
    cudaFuncSetAttribute(fattn_kernel<1>,
                         cudaFuncAttributeMaxDynamicSharedMemorySize, smem_attn);
    cudaFuncSetAttribute(tgemm_kernel<0>,
                         cudaFuncAttributeMaxDynamicSharedMemorySize, smem_gemm);
    cudaFuncSetAttribute(tgemm_kernel<1>,
                         cudaFuncAttributeMaxDynamicSharedMemorySize, smem_gemm);
    cudaFuncSetAttribute(tgemm_kernel<2>,
                         cudaFuncAttributeMaxDynamicSharedMemorySize, smem_gemm);

    // tf32 pre-conversion of GEMM operands
    conv_tf32_kernel<0><<<(int)((size_t)MROWS * TC / 4 / 256), 256>>>(x);
    conv_tf32_kernel<1><<<(int)((size_t)TC * 2 * TC / 4 / 256), 256>>>(W_attn);
    conv_tf32_kernel<2><<<(int)((size_t)TC * TC / 4 / 256), 256>>>(W_k2);
    conv_tf32_kernel<3><<<(int)((size_t)TC * TC / 4 / 256), 256>>>(W_proj);
    prep_v32_kernel<<<dim3(TT / 64, BHN), 256>>>(x);

    tgemm_kernel<0><<<dim3(2 * TC / 128, MROWS / 128), 256, smem_gemm>>>(
        nullptr, MROWS, 2 * TC, TC);
    tgemm_kernel<1><<<dim3(TC / 128, MROWS / 128), 256, smem_gemm>>>(
        nullptr, MROWS, TC, TC);
    fattn_kernel<0><<<dim3(TT / 64, BHN), 256, smem_attn>>>(x);
    fattn_kernel<1><<<dim3(TT / 64, BHN), 256, smem_attn>>>(x);
    tgemm_kernel<2><<<dim3(TC / 128, MROWS / 128), 256, smem_gemm>>>(
        out, MROWS, TC, TC);
}

// round 9
// speedup vs baseline: 1.2545x; 1.0183x over previous
#include <cuda_runtime.h>
#include <math.h>
#include <stdint.h>

#define TB 2
#define TT 2048
#define TC 1024
#define NH 16
#define HD 64
#define BHN (TB*NH)
#define MROWS (TB*TT)
#define SCALE 0.125f

#define NELEM ((size_t)BHN*TT*HD)

// Frag-major attention operands (tf32 words)
__device__ __align__(16) uint32_t g_qsh[NELEM], g_qsl[NELEM];  // q*scale hi/lo
__device__ __align__(16) uint32_t g_kfr[2*NELEM];   // k hi/lo interleaved uint4
__device__ __align__(16) uint32_t g_kafr[2*NELEM];  // ka hi/lo interleaved
__device__ __align__(16) uint32_t g_v32[NELEM];     // tf32(x) V-frag layout
__device__ __align__(16) uint32_t g_e32[NELEM];     // tf32(x[s+1]-y[s])
__device__ __align__(16) float    g_y[NELEM];
// tf32 GEMM operands (pre-converted once)
__device__ __align__(16) uint32_t g_xt[(size_t)MROWS*TC];
__device__ __align__(16) uint32_t g_wat[(size_t)TC*2*TC];
__device__ __align__(16) uint32_t g_wk2[(size_t)TC*TC];
__device__ __align__(16) uint32_t g_wpr[(size_t)TC*TC];
__device__ __align__(16) uint32_t g_ysumt[(size_t)TB*TT*TC];

__device__ __forceinline__ uint32_t f2tf32(float f) {
    uint32_t u;
    asm volatile("cvt.rna.tf32.f32 %0, %1;" : "=r"(u) : "f"(f));
    return u;
}
__device__ __forceinline__ void split_tf32(float v, uint32_t& hi, uint32_t& lo) {
    hi = f2tf32(v);
    lo = f2tf32(v - __uint_as_float(hi));
}
__device__ __forceinline__ void mma_tf32(float c[4], const uint32_t a[4],
                                         const uint32_t b[2]) {
    asm volatile(
        "mma.sync.aligned.m16n8k8.row.col.f32.tf32.tf32.f32 "
        "{%0,%1,%2,%3}, {%4,%5,%6,%7}, {%8,%9}, {%0,%1,%2,%3};"
        : "+f"(c[0]), "+f"(c[1]), "+f"(c[2]), "+f"(c[3])
        : "r"(a[0]), "r"(a[1]), "r"(a[2]), "r"(a[3]), "r"(b[0]), "r"(b[1]));
}
__device__ __forceinline__ uint32_t s2u(const void* p) {
    return (uint32_t)__cvta_generic_to_shared(p);
}
__device__ __forceinline__ void cp_async16(uint32_t dst, const void* src) {
    asm volatile("cp.async.cg.shared.global [%0], [%1], 16;"
                 :: "r"(dst), "l"(src));
}
#define CP_COMMIT() asm volatile("cp.async.commit_group;")
#define CP_WAIT0()  asm volatile("cp.async.wait_group 0;" ::: "memory")
#define CP_WAIT1()  asm volatile("cp.async.wait_group 1;" ::: "memory")

// ---- frag-layout index helpers ----
__device__ __forceinline__ size_t qfrag_idx(int tt, int dd) {
    int lane = ((tt & 7) << 2) | (dd & 3);
    int word = (((dd >> 3) + (lane & 7)) & 7) * 4
             + ((tt >> 3) & 1) + (((dd >> 2) & 1) << 1);
    return ((size_t)(tt >> 4)) * 1024 + lane * 32 + word;
}
__device__ __forceinline__ size_t kfr_idx(int s, int d) {
    int lane = ((s & 7) << 2) | (d & 3);
    int word = (((d >> 3) + (lane & 7)) & 7) * 4 + ((d >> 2) & 1);
    return ((size_t)(s >> 3)) * 1024 + lane * 32 + word;
}
__device__ __forceinline__ size_t vfrag_idx(int s, int d) {
    int lane = ((d & 7) << 2) | (s & 3);
    int n = d >> 3;
    int grp = ((s >> 2) & 1) * 2 + (n >> 2);
    int word = ((grp + (lane >> 1)) & 3) * 4 + (n & 3);
    return ((size_t)(s >> 3)) * 512 + lane * 16 + word;
}
__device__ __forceinline__ void store_q(int bh, int tt, int dd, float qraw) {
    float qs = qraw * SCALE;
    size_t f = (size_t)bh * (TT * 64) + qfrag_idx(tt, dd);
    uint32_t h, l;
    split_tf32(qs, h, l);
    g_qsh[f] = h; g_qsl[f] = l;
}
__device__ __forceinline__ void store_kfr(uint32_t* arr, int bh, int tt,
                                          int dd, float v) {
    size_t f = (size_t)bh * (TT * 128) + kfr_idx(tt, dd);
    uint32_t h, l;
    split_tf32(v, h, l);
    arr[f] = h; arr[f + 2] = l;
}

// ---------------------------------------------------------------------------
// ONE prep kernel: tf32 conversions of x/W_attn/W_k2/W_proj + V-frag scatter.
// Block-range dispatch; 9216 blocks total, all independent.
// ---------------------------------------------------------------------------
__global__ __launch_bounds__(256)
void prep_all_kernel(const float* __restrict__ x,
                     const float* __restrict__ W_attn,
                     const float* __restrict__ W_k2,
                     const float* __restrict__ W_proj)
{
    __shared__ uint32_t vs[4096];
    const int bid = blockIdx.x;
    const int tid = threadIdx.x;

    if (bid < 8192) {
        const float* src;
        uint32_t* dst;
        size_t i;
        if (bid < 4096)      { src = x;      dst = g_xt;  i = (size_t)bid * 256 + tid; }
        else if (bid < 6144) { src = W_attn; dst = g_wat; i = (size_t)(bid - 4096) * 256 + tid; }
        else if (bid < 7168) { src = W_k2;   dst = g_wk2; i = (size_t)(bid - 6144) * 256 + tid; }
        else                 { src = W_proj; dst = g_wpr; i = (size_t)(bid - 7168) * 256 + tid; }
        float4 v = ((const float4*)src)[i];
        ((uint4*)dst)[i] = make_uint4(f2tf32(v.x), f2tf32(v.y),
                                      f2tf32(v.z), f2tf32(v.w));
    } else {
        // V-frag prep via smem bounce
        int p = bid - 8192;
        int s0 = (p & 31) * 64;
        int bh = p >> 5;
        int b = bh >> 4, h = bh & 15;
        int lr = tid >> 4, lc4 = (tid & 15) << 2;
#pragma unroll
        for (int it = 0; it < 4; it++) {
            int r = lr + it * 16;
            float4 v = *(const float4*)(x + ((size_t)b * TT + s0 + r) * TC + h * 64 + lc4);
            vs[vfrag_idx(r, lc4 + 0)] = f2tf32(v.x);
            vs[vfrag_idx(r, lc4 + 1)] = f2tf32(v.y);
            vs[vfrag_idx(r, lc4 + 2)] = f2tf32(v.z);
            vs[vfrag_idx(r, lc4 + 3)] = f2tf32(v.w);
        }
        __syncthreads();
        uint32_t* dst = g_v32 + (size_t)bh * (TT * 64) + (size_t)s0 * 64;
#pragma unroll
        for (int k = 0; k < 4; k++) {
            int o = (tid + k * 256) * 4;
            *(uint4*)(dst + o) = *(const uint4*)(vs + o);
        }
    }
}

// ---------------------------------------------------------------------------
// TF32 GEMM, 3-stage cp.async pipeline, tf32 operands.
// MODE 0 (fused): g_xt @ [W_attn | W_k2], N=3072.
//   cols [0,1024): q frags; [1024,2048): k frags; [2048,3072): ka frags.
// MODE 2: g_ysumt @ g_wpr -> Cout.
// smem: As [3][128][20] + Bs [3][16][136] = 56832 B dynamic
// ---------------------------------------------------------------------------
template<int MODE>
__global__ __launch_bounds__(256)
void tgemm_kernel(float* __restrict__ Cout, int M, int N, int K)
{
    extern __shared__ uint32_t smg[];
    const int tid = threadIdx.x;
    const int lane = tid & 31;
    const int warp = tid >> 5;
    const int warpM = warp >> 2, warpN = warp & 3;
    const int g = lane >> 2, t = lane & 3;
    const int bm = blockIdx.y * 128, bn = blockIdx.x * 128;

    const uint32_t* Ap = (MODE == 2) ? g_ysumt : g_xt;
    const uint32_t* Bw;
    int Nb, bnn;
    if (MODE == 0) {
        if (bn < 2 * TC) { Bw = g_wat; Nb = 2 * TC; bnn = bn; }
        else             { Bw = g_wk2; Nb = TC;     bnn = bn - 2 * TC; }
    } else {
        Bw = g_wpr; Nb = N; bnn = bn;
    }

    float acc[4][4][4];
#pragma unroll
    for (int i = 0; i < 4; i++)
#pragma unroll
        for (int j = 0; j < 4; j++)
#pragma unroll
            for (int r = 0; r < 4; r++) acc[i][j][r] = 0.f;

    auto issue = [&](int kt, int st) {
#pragma unroll
        for (int l = 0; l < 2; l++) {
            int id = tid + l * 256;
            int ar = id >> 2, ak = (id & 3) << 2;
            cp_async16(s2u(smg + st * 2560 + ar * 20 + ak),
                       Ap + (size_t)(bm + ar) * K + kt + ak);
            int br = id >> 5, bc = (id & 31) << 2;
            cp_async16(s2u(smg + 7680 + st * 2176 + br * 136 + bc),
                       Bw + (size_t)(kt + br) * Nb + bnn + bc);
        }
        CP_COMMIT();
    };

    issue(0, 0);
    issue(16, 1);
    const int nk = K >> 4;

    for (int i = 0; i < nk; i++) {
        const int st = i % 3;
        const uint32_t* Asb = smg + st * 2560;
        const uint32_t* Bsb = smg + 7680 + st * 2176;
        if (i + 1 < nk) { CP_WAIT1(); } else { CP_WAIT0(); }
        __syncthreads();
#pragma unroll
        for (int ks = 0; ks < 2; ks++) {
            const int k0 = ks * 8;
            uint32_t af[4][4], bf[4][2];
#pragma unroll
            for (int i4 = 0; i4 < 4; i4++) {
                int m0 = warpM * 64 + i4 * 16;
                af[i4][0] = Asb[(m0 + g) * 20 + k0 + t];
                af[i4][1] = Asb[(m0 + g + 8) * 20 + k0 + t];
                af[i4][2] = Asb[(m0 + g) * 20 + k0 + t + 4];
                af[i4][3] = Asb[(m0 + g + 8) * 20 + k0 + t + 4];
            }
#pragma unroll
            for (int j = 0; j < 4; j++) {
                int n0 = warpN * 32 + j * 8;
                bf[j][0] = Bsb[(k0 + t) * 136 + n0 + g];
                bf[j][1] = Bsb[(k0 + t + 4) * 136 + n0 + g];
            }
#pragma unroll
            for (int i4 = 0; i4 < 4; i4++)
#pragma unroll
                for (int j = 0; j < 4; j++)
                    mma_tf32(acc[i4][j], af[i4], bf[j]);
        }
        if (i + 2 < nk) issue((i + 2) << 4, (i + 2) % 3);
    }

    // epilogue
#pragma unroll
    for (int i = 0; i < 4; i++) {
#pragma unroll
        for (int j = 0; j < 4; j++) {
            int col = bn + warpN * 32 + j * 8 + t * 2;
#pragma unroll
            for (int half = 0; half < 2; half++) {
                int m = bm + warpM * 64 + i * 16 + g + half * 8;
                float2 v = half == 0 ? make_float2(acc[i][j][0], acc[i][j][1])
                                     : make_float2(acc[i][j][2], acc[i][j][3]);
                if (MODE == 2) {
                    *(float2*)(Cout + (size_t)m * N + col) = v;
                } else {
                    int b = m >> 11;
                    int tt = m & (TT - 1);
                    if (col < TC) {
                        int bh = b * NH + (col >> 6);
                        int dd = col & 63;
                        store_q(bh, tt, dd, v.x);
                        store_q(bh, tt, dd + 1, v.y);
                    } else if (col < 2 * TC) {
                        int nn = col - TC;
                        int bh = b * NH + (nn >> 6);
                        int dd = nn & 63;
                        store_kfr(g_kfr, bh, tt, dd, v.x);
                        store_kfr(g_kfr, bh, tt, dd + 1, v.y);
                    } else {
                        int nn = col - 2 * TC;
                        int bh = b * NH + (nn >> 6);
                        int dd = nn & 63;
                        float ka0 = 1.f / (1.f + __expf(-0.0025f * v.x));
                        float ka1 = 1.f / (1.f + __expf(-0.0025f * v.y));
                        store_kfr(g_kafr, bh, tt, dd, ka0);
                        store_kfr(g_kafr, bh, tt, dd + 1, ka1);
                    }
                }
            }
        }
    }
}

// ---------------------------------------------------------------------------
// Fused tensor-core attention (unchanged from round 8).
// ---------------------------------------------------------------------------
template<int ARMA>
__global__ __launch_bounds__(256)
void fattn_kernel(const float* __restrict__ x)
{
    extern __shared__ uint32_t smu[];
    uint32_t* Qh = smu;
    uint32_t* Ql = Qh + 4096;
    uint32_t* Kf = Ql + 4096;
    uint32_t* Vv = Kf + 8192;

    const int tid = threadIdx.x;
    const int lane = tid & 31;
    const int warp = tid >> 5;
    const int wm = warp >> 1;
    const int wn = warp & 1;
    const int g = lane >> 2;
    const int t = lane & 3;

    const int bh = blockIdx.y;
    const int b = bh >> 4, h = bh & 15;
    const int qb = (int)gridDim.x - 1 - (int)blockIdx.x;
    const int q0 = qb * 64;

    const size_t bhoff = (size_t)bh * (TT * 64);
    const uint32_t* kf_g = (ARMA ? g_kafr : g_kfr) + (size_t)bh * (TT * 128);
    const uint32_t* v_g  = (ARMA ? g_e32 : g_v32) + bhoff;
    const float* yb = g_y + (size_t)bh * TT * HD;
    const float* vx = x + (size_t)b * TT * TC + h * HD;

    const uint32_t Qh_s = s2u(Qh), Ql_s = s2u(Ql);
    const uint32_t Kf_s = s2u(Kf), Vv_s = s2u(Vv);

    if (ARMA) {
        const uint32_t* qhT = g_qsh + bhoff + (size_t)q0 * 64;
        const uint32_t* qlT = g_qsl + bhoff + (size_t)q0 * 64;
#pragma unroll
        for (int k = 0; k < 4; k++) {
            int o = (tid + k * 256) * 4;
            uint4 hv = *(const uint4*)(qhT + o);
            uint4 lv = *(const uint4*)(qlT + o);
            uint32_t oh[4], ol[4];
            float qs, qa;
            qs = __uint_as_float(hv.x) + __uint_as_float(lv.x);
            qa = fminf(qs, 0.02f * qs); split_tf32(qa, oh[0], ol[0]);
            qs = __uint_as_float(hv.y) + __uint_as_float(lv.y);
            qa = fminf(qs, 0.02f * qs); split_tf32(qa, oh[1], ol[1]);
            qs = __uint_as_float(hv.z) + __uint_as_float(lv.z);
            qa = fminf(qs, 0.02f * qs); split_tf32(qa, oh[2], ol[2]);
            qs = __uint_as_float(hv.w) + __uint_as_float(lv.w);
            qa = fminf(qs, 0.02f * qs); split_tf32(qa, oh[3], ol[3]);
            *(uint4*)(Qh + o) = make_uint4(oh[0], oh[1], oh[2], oh[3]);
            *(uint4*)(Ql + o) = make_uint4(ol[0], ol[1], ol[2], ol[3]);
        }
    } else {
        const uint32_t* qhT = g_qsh + bhoff + (size_t)q0 * 64;
        const uint32_t* qlT = g_qsl + bhoff + (size_t)q0 * 64;
#pragma unroll
        for (int k = 0; k < 4; k++) {
            int o = (tid + k * 256) * 4;
            cp_async16(Qh_s + o * 4, qhT + o);
            cp_async16(Ql_s + o * 4, qlT + o);
        }
    }

    float O[8][4];
#pragma unroll
    for (int n = 0; n < 8; n++)
#pragma unroll
        for (int c = 0; c < 4; c++) O[n][c] = 0.f;
    float m_run[2] = {-1e30f, -1e30f};
    float l_run[2] = {0.f, 0.f};

    const int qrow0 = q0 + wm * 16 + g;
    const int qrow1 = qrow0 + 8;
    const int sw = wn * 32;

    for (int kt = 0; kt <= qb; kt++) {
        const int s0 = kt * 64;
        __syncthreads();

        {
            const uint32_t* kT = kf_g + (size_t)s0 * 128;
            const uint32_t* vT = v_g + (size_t)s0 * 64;
#pragma unroll
            for (int k = 0; k < 8; k++) {
                int o = (tid + k * 256) * 4;
                cp_async16(Kf_s + o * 4, kT + o);
            }
#pragma unroll
            for (int k = 0; k < 4; k++) {
                int o = (tid + k * 256) * 4;
                cp_async16(Vv_s + o * 4, vT + o);
            }
        }
        CP_COMMIT();
        CP_WAIT0();
        __syncthreads();

        float acc[4][4];
#pragma unroll
        for (int nb = 0; nb < 4; nb++)
#pragma unroll
            for (int c = 0; c < 4; c++) acc[nb][c] = 0.f;

#pragma unroll
        for (int c = 0; c < 8; c++) {
            int qoff = wm * 1024 + lane * 32 + ((c + (lane & 7)) & 7) * 4;
            uint4 ahv = *(const uint4*)(Qh + qoff);
            uint4 alv = *(const uint4*)(Ql + qoff);
            uint32_t ah[4] = {ahv.x, ahv.y, ahv.z, ahv.w};
            uint32_t al[4] = {alv.x, alv.y, alv.z, alv.w};
#pragma unroll
            for (int nb = 0; nb < 4; nb++) {
                int koff = (wn * 4 + nb) * 1024 + lane * 32
                         + ((c + (lane & 7)) & 7) * 4;
                uint4 kk = *(const uint4*)(Kf + koff);
                uint32_t bh2[2] = {kk.x, kk.y};
                uint32_t bl2[2] = {kk.z, kk.w};
                mma_tf32(acc[nb], ah, bh2);
                mma_tf32(acc[nb], al, bh2);
                mma_tf32(acc[nb], ah, bl2);
            }
        }

        const bool diag = (kt == qb);
        if (diag) {
#pragma unroll
            for (int nb = 0; nb < 4; nb++) {
                int colb = s0 + sw + nb * 8 + 2 * t;
#pragma unroll
                for (int c = 0; c < 4; c++) {
                    int cc = colb + (c & 1);
                    int rr = (c >= 2) ? qrow1 : qrow0;
                    if (ARMA) { if (cc >= rr) acc[nb][c] = 0.f; }
                    else      { if (cc >  rr) acc[nb][c] = -1e30f; }
                }
            }
        }

        if (!ARMA) {
            float mt0 = -1e30f, mt1 = -1e30f;
#pragma unroll
            for (int nb = 0; nb < 4; nb++) {
                mt0 = fmaxf(mt0, fmaxf(acc[nb][0], acc[nb][1]));
                mt1 = fmaxf(mt1, fmaxf(acc[nb][2], acc[nb][3]));
            }
#pragma unroll
            for (int off = 1; off <= 2; off <<= 1) {
                mt0 = fmaxf(mt0, __shfl_xor_sync(0xffffffffu, mt0, off));
                mt1 = fmaxf(mt1, __shfl_xor_sync(0xffffffffu, mt1, off));
            }
            float mn0 = fmaxf(m_run[0], mt0);
            float mn1 = fmaxf(m_run[1], mt1);
            float corr0 = __expf(m_run[0] - mn0);
            float corr1 = __expf(m_run[1] - mn1);
            m_run[0] = mn0; m_run[1] = mn1;

            float ls0 = 0.f, ls1 = 0.f;
#pragma unroll
            for (int nb = 0; nb < 4; nb++) {
                float p0 = __expf(acc[nb][0] - mn0);
                float p1 = __expf(acc[nb][1] - mn0);
                float p2 = __expf(acc[nb][2] - mn1);
                float p3 = __expf(acc[nb][3] - mn1);
                if (diag) {
                    int colb = s0 + sw + nb * 8 + 2 * t;
                    if (colb     > qrow0) p0 = 0.f;
                    if (colb + 1 > qrow0) p1 = 0.f;
                    if (colb     > qrow1) p2 = 0.f;
                    if (colb + 1 > qrow1) p3 = 0.f;
                }
                acc[nb][0] = p0; acc[nb][1] = p1;
                acc[nb][2] = p2; acc[nb][3] = p3;
                ls0 += p0 + p1;
                ls1 += p2 + p3;
            }
#pragma unroll
            for (int off = 1; off <= 2; off <<= 1) {
                ls0 += __shfl_xor_sync(0xffffffffu, ls0, off);
                ls1 += __shfl_xor_sync(0xffffffffu, ls1, off);
            }
            l_run[0] = l_run[0] * corr0 + ls0;
            l_run[1] = l_run[1] * corr1 + ls1;
#pragma unroll
            for (int n = 0; n < 8; n++) {
                O[n][0] *= corr0; O[n][1] *= corr0;
                O[n][2] *= corr1; O[n][3] *= corr1;
            }
        }

#pragma unroll
        for (int nb = 0; nb < 4; nb++) {
            int src0 = (lane & ~3) | (t >> 1);
            int src2 = src0 + 2;
            float s00 = __shfl_sync(0xffffffffu, acc[nb][0], src0);
            float s01 = __shfl_sync(0xffffffffu, acc[nb][1], src0);
            float s20 = __shfl_sync(0xffffffffu, acc[nb][0], src2);
            float s21 = __shfl_sync(0xffffffffu, acc[nb][1], src2);
            float s10 = __shfl_sync(0xffffffffu, acc[nb][2], src0);
            float s11 = __shfl_sync(0xffffffffu, acc[nb][3], src0);
            float s30 = __shfl_sync(0xffffffffu, acc[nb][2], src2);
            float s31 = __shfl_sync(0xffffffffu, acc[nb][3], src2);
            bool odd = (t & 1);
            float pa0 = odd ? s01 : s00;
            float pa1 = odd ? s11 : s10;
            float pa2 = odd ? s21 : s20;
            float pa3 = odd ? s31 : s30;
            uint32_t ah[4], al[4];
            split_tf32(pa0, ah[0], al[0]);
            split_tf32(pa1, ah[1], al[1]);
            split_tf32(pa2, ah[2], al[2]);
            split_tf32(pa3, ah[3], al[3]);

            int vb = (wn * 4 + nb) * 512 + lane * 16;
            uint32_t vfr[16];
#pragma unroll
            for (int G = 0; G < 4; G++) {
                uint4 t4 = *(const uint4*)(Vv + vb + ((G + (lane >> 1)) & 3) * 4);
                vfr[G * 4 + 0] = t4.x; vfr[G * 4 + 1] = t4.y;
                vfr[G * 4 + 2] = t4.z; vfr[G * 4 + 3] = t4.w;
            }
#pragma unroll
            for (int n = 0; n < 8; n++) {
                uint32_t bv[2] = {vfr[n], vfr[8 + n]};
                mma_tf32(O[n], ah, bv);
                mma_tf32(O[n], al, bv);
            }
        }
    }

    __syncthreads();
    const int r0l = wm * 16 + g, r1l = r0l + 8;
    float* Ob = (float*)Qh;
    if (!ARMA) {
        float* ml = (float*)Kf;
        if (t == 0) {
            ml[r0l * 4 + wn * 2 + 0] = m_run[0];
            ml[r0l * 4 + wn * 2 + 1] = l_run[0];
            ml[r1l * 4 + wn * 2 + 0] = m_run[1];
            ml[r1l * 4 + wn * 2 + 1] = l_run[1];
        }
        __syncthreads();
        float ma0 = ml[r0l * 4 + 0], la0 = ml[r0l * 4 + 1];
        float mb0 = ml[r0l * 4 + 2], lb0 = ml[r0l * 4 + 3];
        float ma1 = ml[r1l * 4 + 0], la1 = ml[r1l * 4 + 1];
        float mb1 = ml[r1l * 4 + 2], lb1 = ml[r1l * 4 + 3];
        float mm0 = fmaxf(ma0, mb0), mm1 = fmaxf(ma1, mb1);
        float lt0 = la0 * __expf(ma0 - mm0) + lb0 * __expf(mb0 - mm0);
        float lt1 = la1 * __expf(ma1 - mm1) + lb1 * __expf(mb1 - mm1);
        float f0 = __expf(m_run[0] - mm0);
        float f1 = __expf(m_run[1] - mm1);
#pragma unroll
        for (int n = 0; n < 8; n++) {
            O[n][0] *= f0; O[n][1] *= f0;
            O[n][2] *= f1; O[n][3] *= f1;
        }
        if (wn == 1) {
#pragma unroll
            for (int n = 0; n < 8; n++) {
                int col = n * 8 + 2 * t;
                *(float2*)(Ob + r0l * 66 + col) = make_float2(O[n][0], O[n][1]);
                *(float2*)(Ob + r1l * 66 + col) = make_float2(O[n][2], O[n][3]);
            }
        }
        __syncthreads();
        if (wn == 0) {
            float inv0 = 1.f / lt0, inv1 = 1.f / lt1;
            float* yo = g_y + (size_t)bh * TT * HD;
            uint32_t* eo = g_e32 + bhoff;
#pragma unroll
            for (int n = 0; n < 8; n++) {
                int col = n * 8 + 2 * t;
                float2 p0 = *(const float2*)(Ob + r0l * 66 + col);
                float2 p1 = *(const float2*)(Ob + r1l * 66 + col);
                float y00 = (O[n][0] + p0.x) * inv0;
                float y01 = (O[n][1] + p0.y) * inv0;
                float y10 = (O[n][2] + p1.x) * inv1;
                float y11 = (O[n][3] + p1.y) * inv1;
                *(float2*)(yo + (size_t)qrow0 * HD + col) = make_float2(y00, y01);
                *(float2*)(yo + (size_t)qrow1 * HD + col) = make_float2(y10, y11);
                float e00 = 0.f, e01 = 0.f, e10 = 0.f, e11 = 0.f;
                if (qrow0 + 1 < TT) {
                    float2 xv = *(const float2*)(vx + (size_t)(qrow0 + 1) * TC + col);
                    e00 = xv.x - y00; e01 = xv.y - y01;
                }
                if (qrow1 + 1 < TT) {
                    float2 xv = *(const float2*)(vx + (size_t)(qrow1 + 1) * TC + col);
                    e10 = xv.x - y10; e11 = xv.y - y11;
                }
                eo[vfrag_idx(qrow0, col)]     = f2tf32(e00);
                eo[vfrag_idx(qrow0, col + 1)] = f2tf32(e01);
                eo[vfrag_idx(qrow1, col)]     = f2tf32(e10);
                eo[vfrag_idx(qrow1, col + 1)] = f2tf32(e11);
            }
        }
    } else {
        if (wn == 1) {
#pragma unroll
            for (int n = 0; n < 8; n++) {
                int col = n * 8 + 2 * t;
                *(float2*)(Ob + r0l * 66 + col) = make_float2(O[n][0], O[n][1]);
                *(float2*)(Ob + r1l * 66 + col) = make_float2(O[n][2], O[n][3]);
            }
        }
        __syncthreads();
        if (wn == 0) {
            uint32_t* yo = g_ysumt + (size_t)b * TT * TC + h * HD;
#pragma unroll
            for (int n = 0; n < 8; n++) {
                int col = n * 8 + 2 * t;
                float2 p0 = *(const float2*)(Ob + r0l * 66 + col);
                float2 p1 = *(const float2*)(Ob + r1l * 66 + col);
                float2 y0 = *(const float2*)(yb + (size_t)qrow0 * HD + col);
                float2 y1 = *(const float2*)(yb + (size_t)qrow1 * HD + col);
                *(uint2*)(yo + (size_t)qrow0 * TC + col) =
                    make_uint2(f2tf32(O[n][0] + p0.x + y0.x),
                               f2tf32(O[n][1] + p0.y + y0.y));
                *(uint2*)(yo + (size_t)qrow1 * TC + col) =
                    make_uint2(f2tf32(O[n][2] + p1.x + y1.x),
                               f2tf32(O[n][3] + p1.y + y1.y));
            }
        }
    }
}

// ---------------------------------------------------------------------------
extern "C" void kernel_launch(void* const* d_in, const int* in_sizes, int n_in,
                              void* d_out, int out_size)
{
    (void)in_sizes; (void)n_in; (void)out_size;
    const float* x      = (const float*)d_in[0];
    const float* W_attn = (const float*)d_in[1];
    const float* W_k2   = (const float*)d_in[2];
    const float* W_proj = (const float*)d_in[3];
    float* out = (float*)d_out;

    const int smem_attn = 20480 * (int)sizeof(uint32_t);  // 81920 B
    const int smem_gemm = (3 * 2560 + 3 * 2176) * (int)sizeof(uint32_t);  // 56832 B
    cudaFuncSetAttribute(fattn_kernel<0>,
                         cudaFuncAttributeMaxDynamicSharedMemorySize, smem_attn);
    cudaFuncSetAttribute(fattn_kernel<1>,
                         cudaFuncAttributeMaxDynamicSharedMemorySize, smem_attn);
    cudaFuncSetAttribute(tgemm_kernel<0>,
                         cudaFuncAttributeMaxDynamicSharedMemorySize, smem_gemm);
    cudaFuncSetAttribute(tgemm_kernel<2>,
                         cudaFuncAttributeMaxDynamicSharedMemorySize, smem_gemm);

    // 1. all prep work (tf32 conversions + V-frag scatter) in one grid
    prep_all_kernel<<<9216, 256>>>(x, W_attn, W_k2, W_proj);
    // 2. fused qk + k2 GEMM (N = 3072)
    tgemm_kernel<0><<<dim3(3 * TC / 128, MROWS / 128), 256, smem_gemm>>>(
        nullptr, MROWS, 3 * TC, TC);
    // 3-4. attention passes
    fattn_kernel<0><<<dim3(TT / 64, BHN), 256, smem_attn>>>(x);
    fattn_kernel<1><<<dim3(TT / 64, BHN), 256, smem_attn>>>(x);
    // 5. output projection
    tgemm_kernel<2><<<dim3(TC / 128, MROWS / 128), 256, smem_gemm>>>(
        out, MROWS, TC, TC);
}